// round 15
// baseline (speedup 1.0000x reference)
#include <cuda_runtime.h>
#include <cuda_fp16.h>
#include <math.h>
#include <stdint.h>

// ---------------- problem constants ----------------
#define NB 16
#define HW 4096
#define CHW (128*HW)          // 524288
#define AUXC 277
#define AUXK 320

// ---------------- weight pack offsets (halfs) ----------------
#define WO_QKV  0             // [384][128]
#define WO_GB1  49152         // [256][320]  fused (S|Bh)·E
#define WO_B1   131072        // [128][256]
#define WO_GB2  163840        // [256][320]
#define WO_B2   245760        // [128][256]
#define WO_SC   278528        // [128][1152] plane-major
#define WO_BI1  425984
#define WO_BI2  573440
#define W_TOTAL 720896

// ---------------- scratch ----------------
__device__ __align__(256) half  g_wh  [W_TOTAL];
__device__ float g_qkvb[384];
__device__ float g_gbb1[256];
__device__ float g_gbb2[256];
__device__ __align__(256) half  g_auxh[(long)NB*AUXK*HW];
__device__ __align__(256) half  g_xh  [(long)NB*CHW];
__device__ __align__(256) half  g_t0h [(long)NB*3*CHW];
__device__ __align__(256) half  g_gamh[(long)NB*CHW];
__device__ __align__(256) half  g_beth[(long)NB*CHW];
__device__ __align__(256) half  g_midh[(long)NB*CHW];
__device__ __align__(256) half  g_oh  [(long)NB*CHW];
__device__ __align__(256) half  g_gfh [(long)NB*CHW];
__device__ __align__(256) half  g_tmph[(long)NB*CHW];
__device__ __align__(256) half  g_qp1 [NB*1024L*256];
__device__ __align__(256) half  g_kp1 [NB*1024L*256];
__device__ __align__(256) half  g_vp1 [NB*1024L*256];
__device__ __align__(256) half  g_qp2 [NB*256L*1024];
__device__ __align__(256) half  g_kp2 [NB*256L*1024];
__device__ __align__(256) half  g_vp2 [NB*256L*1024];
__device__ __align__(256) half  g_s1h [NB*1024L*1024];
__device__ __align__(256) half  g_s2h [NB*256L*256];
__device__ float g_stats[96];
__device__ float g_acc  [96];

// ---------------- epilogue modes ----------------
#define EP_LIN   0
#define EP_GB    1
#define EP_QKV3  2
#define EP_ADN   3
#define EP_SCORE 4
#define EP_PV1   5
#define EP_PV2   6
#define EP_TANH  7
#define EP_GELU  8
#define EP_FINAL 9

// ---------------- smem geometry (halfs), Kt = 64 ----------------
#define A_LDH 72
#define A_ROWB 144
#define BK_LDH 136
#define BK_ROWB 272
#define STAGE_HALFS 18432
#define STAGE_BYTES 36864
#define B_OFF_H 9216
#define GSM_BYTES (2*STAGE_BYTES)

// ---------------- asm helpers ----------------
__device__ __forceinline__ uint32_t smem_u32(const void* p) {
    uint32_t a;
    asm("{ .reg .u64 t; cvta.to.shared.u64 t, %1; cvt.u32.u64 %0, t; }" : "=r"(a) : "l"(p));
    return a;
}
__device__ __forceinline__ void ldsm_x4(uint32_t* r, uint32_t addr) {
    asm volatile("ldmatrix.sync.aligned.m8n8.x4.shared.b16 {%0,%1,%2,%3}, [%4];"
                 : "=r"(r[0]), "=r"(r[1]), "=r"(r[2]), "=r"(r[3]) : "r"(addr));
}
__device__ __forceinline__ void ldsm_x4t(uint32_t* r, uint32_t addr) {
    asm volatile("ldmatrix.sync.aligned.m8n8.x4.trans.shared.b16 {%0,%1,%2,%3}, [%4];"
                 : "=r"(r[0]), "=r"(r[1]), "=r"(r[2]), "=r"(r[3]) : "r"(addr));
}
__device__ __forceinline__ void mma_f16(float* c,
                                        uint32_t a0, uint32_t a1, uint32_t a2, uint32_t a3,
                                        uint32_t b0, uint32_t b1) {
    asm volatile(
        "mma.sync.aligned.m16n8k16.row.col.f32.f16.f16.f32 "
        "{%0,%1,%2,%3}, {%4,%5,%6,%7}, {%8,%9}, {%0,%1,%2,%3};"
        : "+f"(c[0]), "+f"(c[1]), "+f"(c[2]), "+f"(c[3])
        : "r"(a0), "r"(a1), "r"(a2), "r"(a3), "r"(b0), "r"(b1));
}

// ---------------- GEMM params ----------------
struct GP {
    const half* A; int lda; long sA;
    const half* B; int ldb; long sB;
    int N; long sC; int nkt;
    int mode; float scale; int dil; int lng;
    const float* bias;
    const half* t0h; const half* gamh; const half* beth; const float* stats;
    const float* xres; const half* midh; const half* gfh;
    float* of; half* ohh; half* ohh2;
    half* d1q; half* d1k; half* d1v;
    half* d2q; half* d2k; half* d2v;
    float* acc;
    // conv merged variant (blockIdx.y == 1)
    const half* A2; const float* bias2c; int dil2; int mode2c;
    // secondary GEMM (merged launches)
    const half* A2g; long sA2;
    const half* B2g; int ldb2; long sB2;
    int N2, nkt2, mT2, lda2, mT1;
    long sC2; float scale2; half* out2;
    int mode2; const float* bias2;
};

// ================= fp16 tensor-core GEMM, Kt=64 =================
// TRANSB=0, CONV=0 : C[m,n] = A[m,k] * B[k,n]   (B k-major smem, ldmatrix.trans)
// TRANSB=1         : C[m,n] = A[m,k] * B[n,k]   (B n-major smem, ldmatrix)
// CONV=1           : B gathered plane-major from NCHW-half activations; grid.y selects variant
template<bool TRANSB, bool CONV>
__global__ void __launch_bounds__(256)
hgemm15(GP g) {
    extern __shared__ __align__(16) half sm[];
    int bb = blockIdx.z;
    int n0 = blockIdx.x * 128;
    int m0 = CONV ? 0 : blockIdx.y * 128;

    const half* Aw = g.A;
    const half* Bw = g.B;
    int lda = g.lda, ldb = g.ldb;
    long sA = g.sA, sB = g.sB, sC = g.sC;
    int NN = g.N, nkt = g.nkt;
    int dil = g.dil;
    int mode = g.mode;
    float scale = g.scale;
    const float* biasL = g.bias;
    half* ohhL = g.ohh;

    if (CONV && blockIdx.y == 1) {
        Aw = g.A2; dil = g.dil2; mode = g.mode2c; biasL = g.bias2c; ohhL = g.ohh2;
    }
    if (TRANSB && g.N2 && blockIdx.y == gridDim.y - 1) {
        int t2x = g.N2 >> 7;
        int id = blockIdx.x;
        if (id >= g.mT2 * t2x) return;
        m0 = (id / t2x) * 128;
        n0 = (id % t2x) * 128;
        Aw = g.A2g; Bw = g.B2g;
        lda = g.lda2; ldb = g.ldb2;
        sA = g.sA2; sB = g.sB2; sC = g.sC2;
        NN = g.N2; nkt = g.nkt2; scale = g.scale2;
        ohhL = g.out2;
    }
    if (!TRANSB && !CONV && g.N2) {
        // 1D merged NN launch: grid(prim+sec, 1, z)
        int t1x = NN >> 7;
        int prim = g.mT1 * t1x;
        int id = blockIdx.x;
        if (id < prim) {
            m0 = (id / t1x) * 128;
            n0 = (id % t1x) * 128;
        } else {
            id -= prim;
            int t2x = g.N2 >> 7;
            m0 = (id / t2x) * 128;
            n0 = (id % t2x) * 128;
            Aw = g.A2g; Bw = g.B2g;
            lda = g.lda2; ldb = g.ldb2;
            sA = g.sA2; sB = g.sB2; sC = g.sC2;
            NN = g.N2; nkt = g.nkt2;
            mode = g.mode2; biasL = g.bias2; ohhL = g.out2;
        }
    }
    const half* Ap = Aw + (long)bb * sA;
    const half* Bp = Bw + (long)bb * sB;

    int tid  = threadIdx.x;
    int lane = tid & 31;
    int warp = tid >> 5;
    int wm = (warp >> 2) * 64;
    int wn = (warp & 3) * 32;

    int arow  = tid >> 1;
    int akseg = (tid & 1) * 32;
    int bkr = tid >> 2;
    int bns = (tid & 3) * 32;
    int cn    = tid & 127;
    int ckseg = (tid >> 7) * 32;

    uint32_t sbase = smem_u32(sm);
    int rowsel = lane & 15;
    int colsel = (lane >> 4) * 16;

    uint4 ra[4], rb[4];
    float acc[4][4][4] = {};

    for (int it = 0; it <= nkt; it++) {
        if (it < nkt) {
            int kt = it * 64;
            const half* ar = Ap + (long)(m0 + arow) * lda + kt + akseg;
#pragma unroll
            for (int j = 0; j < 4; j++) ra[j] = *(const uint4*)(ar + j * 8);
            if (CONV) {
                int tap = kt >> 7;
                int cb  = (kt & 127) + ckseg;
                int dy = (tap / 3 - 1) * dil;
                int dx = (tap % 3 - 1) * dil;
                int p = n0 + cn;
                int h = (p >> 6) + dy;
                int w = (p & 63) + dx;
                half rc[32];
                if ((unsigned)h < 64u && (unsigned)w < 64u) {
                    const half* base = Bp + (long)cb * HW + h * 64 + w;
#pragma unroll
                    for (int j = 0; j < 32; j++) rc[j] = base[(long)j * HW];
                } else {
#pragma unroll
                    for (int j = 0; j < 32; j++) rc[j] = __ushort_as_half((unsigned short)0);
                }
#pragma unroll
                for (int j = 0; j < 4; j++) rb[j] = ((uint4*)rc)[j];
            } else if (TRANSB) {
                const half* br = Bp + (long)(n0 + arow) * ldb + kt + akseg;
#pragma unroll
                for (int j = 0; j < 4; j++) rb[j] = *(const uint4*)(br + j * 8);
            } else {
                const half* br = Bp + (long)(kt + bkr) * ldb + n0 + bns;
#pragma unroll
                for (int j = 0; j < 4; j++) rb[j] = *(const uint4*)(br + j * 8);
            }
        }

        if (it > 0) {
            uint32_t stA = sbase + (uint32_t)(((it - 1) & 1) * STAGE_BYTES);
            uint32_t stB = stA + B_OFF_H * 2;
            uint32_t abase = stA + (uint32_t)(wm + rowsel) * A_ROWB + colsel;
#pragma unroll
            for (int ks = 0; ks < 4; ks++) {
                uint32_t af[4][4];
#pragma unroll
                for (int mt = 0; mt < 4; mt++)
                    ldsm_x4(af[mt], abase + mt * 16 * A_ROWB + ks * 32);
                uint32_t bf[2][4];
                if (TRANSB || CONV) {
                    uint32_t bbase = stB + (uint32_t)(wn + rowsel) * A_ROWB + colsel;
#pragma unroll
                    for (int ntp = 0; ntp < 2; ntp++)
                        ldsm_x4(bf[ntp], bbase + ntp * 16 * A_ROWB + ks * 32);
                } else {
                    uint32_t bbase = stB + (uint32_t)(ks * 16 + rowsel) * BK_ROWB
                                   + (uint32_t)(wn + (lane >> 4) * 8) * 2;
#pragma unroll
                    for (int ntp = 0; ntp < 2; ntp++)
                        ldsm_x4t(bf[ntp], bbase + ntp * 32);
                }
#pragma unroll
                for (int mt = 0; mt < 4; mt++) {
#pragma unroll
                    for (int nt = 0; nt < 4; nt++) {
                        int ntp = nt >> 1, par = nt & 1;
                        uint32_t b0, b1;
                        if (TRANSB || CONV) { b0 = bf[ntp][par];     b1 = bf[ntp][par + 2]; }
                        else                { b0 = bf[ntp][par * 2]; b1 = bf[ntp][par * 2 + 1]; }
                        mma_f16(acc[mt][nt],
                                af[mt][0], af[mt][1], af[mt][2], af[mt][3], b0, b1);
                    }
                }
            }
        }

        if (it < nkt) {
            half* stA = sm + (it & 1) * STAGE_HALFS;
            half* stB = stA + B_OFF_H;
            half* da = stA + arow * A_LDH + akseg;
#pragma unroll
            for (int j = 0; j < 4; j++) *(uint4*)(da + j * 8) = ra[j];
            half* db;
            if (CONV)        db = stB + cn * A_LDH + ckseg;
            else if (TRANSB) db = stB + arow * A_LDH + akseg;
            else             db = stB + bkr * BK_LDH + bns;
#pragma unroll
            for (int j = 0; j < 4; j++) *(uint4*)(db + j * 8) = rb[j];
        }
        __syncthreads();
    }

    // ---- epilogue ----
    int r  = lane >> 2;
    int cg = lane & 3;
    long bbC = (long)bb * sC;
    float mu = 0.f, rs = 0.f;
    if (mode == EP_QKV3 || mode == EP_ADN) { mu = g.stats[2 * bb]; rs = g.stats[2 * bb + 1]; }
    int b3 = bb / 3, t3 = bb - 3 * (bb / 3);
    float lsum = 0.f, lsq = 0.f;

    auto emit = [&](float v, int m, int n) {
        long li = (long)m * NN + n;
        if (mode == EP_LIN) {
            float res = v + biasL[m];
            if (g.lng) { lsum += res; lsq += res * res; }
            ohhL[bbC + li] = __float2half_rn(res);
        } else if (mode == EP_GB) {
            float res = v + biasL[m];
            long o = (long)bb * CHW + (long)(m & 127) * HW + n;
            if (m < 128) ohhL  [o] = __float2half_rn(res);
            else         g.ohh2[o] = __float2half_rn(res);
        } else if (mode == EP_QKV3) {
            long ti = bbC + li;
            long gi = (long)b3 * CHW + li;
            float val = (__half2float(g.t0h[ti]) - mu) * rs * __half2float(g.gamh[gi])
                        + v + __half2float(g.beth[gi]);
            half hv = __float2half_rn(val);
            int h = n >> 6, w = n & 63;
            if (m < 64) {
                int tk = (h >> 1) * 32 + (w >> 1);
                int d  = m * 4 + (h & 1) * 2 + (w & 1);
                half* dst = (t3 == 0) ? g.d1q : (t3 == 1) ? g.d1k : g.d1v;
                dst[(long)b3 * (1024L * 256) + (long)tk * 256 + d] = hv;
            } else {
                int tk = (h >> 2) * 16 + (w >> 2);
                int d  = (m - 64) * 16 + (h & 3) * 4 + (w & 3);
                half* dst = (t3 == 0) ? g.d2q : (t3 == 1) ? g.d2k : g.d2v;
                dst[(long)b3 * (256L * 1024) + (long)tk * 1024 + d] = hv;
            }
        } else if (mode == EP_ADN) {
            long gi = bbC + li;
            float res = (__half2float(g.t0h[gi]) - mu) * rs * __half2float(g.gamh[gi])
                        + v + __half2float(g.beth[gi]);
            ohhL[gi] = __float2half_rn(res);
        } else if (mode == EP_SCORE) {
            ohhL[bbC + li] = __float2half_rn(v * scale);
        } else if (mode == EP_PV1) {
            int c  = n >> 2;
            int py = (n >> 1) & 1, px = n & 1;
            int h = (m >> 5) * 2 + py, w = (m & 31) * 2 + px;
            long tgt = bbC + (long)c * HW + h * 64 + w;
            float res = g.xres[tgt] + v;
            lsum += res; lsq += res * res;
            ohhL[tgt] = __float2half_rn(res);
        } else if (mode == EP_PV2) {
            int c  = 64 + (n >> 4);
            int py = (n >> 2) & 3, px = n & 3;
            int h = (m >> 4) * 4 + py, w = (m & 15) * 4 + px;
            long tgt = bbC + (long)c * HW + h * 64 + w;
            float res = g.xres[tgt] + v;
            lsum += res; lsq += res * res;
            ohhL[tgt] = __float2half_rn(res);
        } else if (mode == EP_TANH) {
            ohhL[bbC + li] = __float2half_rn(tanhf(v + biasL[m]));
        } else if (mode == EP_GELU) {
            float u = v + biasL[m];
            ohhL[bbC + li] = __float2half_rn(0.5f * u * (1.f + erff(u * 0.70710678118654752f)));
        } else { // EP_FINAL
            long gi = bbC + li;
            g.of[gi] = __half2float(g.midh[gi]) * __half2float(g.gfh[gi]) + v + biasL[m];
        }
    };

#pragma unroll
    for (int mt = 0; mt < 4; mt++) {
#pragma unroll
        for (int nt = 0; nt < 4; nt++) {
            int m1 = m0 + wm + mt * 16 + r;
            int m2 = m1 + 8;
            int nn = n0 + wn + nt * 8 + cg * 2;
            emit(acc[mt][nt][0], m1, nn);
            emit(acc[mt][nt][1], m1, nn + 1);
            emit(acc[mt][nt][2], m2, nn);
            emit(acc[mt][nt][3], m2, nn + 1);
        }
    }

    // ---- fused LN partial-stats reduction ----
    if (g.lng) {
#pragma unroll
        for (int o = 16; o; o >>= 1) {
            lsum += __shfl_xor_sync(0xffffffffu, lsum, o);
            lsq  += __shfl_xor_sync(0xffffffffu, lsq,  o);
        }
        float* smf = (float*)sm;
        if (lane == 0) { smf[warp * 2] = lsum; smf[warp * 2 + 1] = lsq; }
        __syncthreads();
        if (warp == 0 && lane < 8) {
            lsum = smf[lane * 2]; lsq = smf[lane * 2 + 1];
#pragma unroll
            for (int o = 4; o; o >>= 1) {
                lsum += __shfl_xor_sync(0xffu, lsum, o);
                lsq  += __shfl_xor_sync(0xffu, lsq,  o);
            }
            if (lane == 0) {
                int grp = (g.lng == 1) ? bb * 3 + (m0 >> 7) : bb;
                atomicAdd(&g.acc[2 * grp],     lsum);
                atomicAdd(&g.acc[2 * grp + 1], lsq);
            }
        }
    }
}

// ================= weight repack + bias pack =================
__global__ void __launch_bounds__(256)
wconv_kernel(const float* qw, const float* kw, const float* vw,
             const float* b1, const float* b2,
             const float* sc, const float* bi1, const float* bi2,
             const float* qb, const float* kb, const float* vb) {
    int i = blockIdx.x * 256 + threadIdx.x;
    if (i >= W_TOTAL) {
        int j = i - W_TOTAL;
        if (j < 384) g_qkvb[j] = j < 128 ? qb[j] : j < 256 ? kb[j - 128] : vb[j - 256];
        return;
    }
    float v;
    if (i < WO_GB1) {
        int t = i >> 14, j = i & 16383;
        v = (t == 0 ? qw : t == 1 ? kw : vw)[j];
    } else if (i < WO_B1) {
        return;
    } else if (i < WO_GB2) {
        v = b1[i - WO_B1];
    } else if (i < WO_B2) {
        return;
    } else if (i < WO_SC) {
        v = b2[i - WO_B2];
    } else {
        int j = i - WO_SC;
        int blk = j / 147456, t = j % 147456;
        int o = t / 1152, rr = t % 1152;
        int tap = rr >> 7, c = rr & 127;
        const float* w = (blk == 0 ? sc : blk == 1 ? bi1 : bi2);
        v = w[((o * 128 + c) * 3 + tap / 3) * 3 + (tap % 3)];
    }
    g_wh[i] = __float2half_rn(v);
}

// ================= tiled fuse, both ADN sets in one launch (grid.z) =================
__global__ void __launch_bounds__(256)
fuse_gb_kernel(const float* e1,  const float* sw1, const float* bw1,
               const float* eb1, const float* sb1, const float* bb1,
               const float* e2,  const float* sw2, const float* bw2,
               const float* eb2, const float* sb2, const float* bb2,
               half* dstW1, float* dstB1, half* dstW2, float* dstB2) {
    const float *e, *sw, *bw, *eb, *sb, *bbv;
    half* dstW; float* dstB;
    if (blockIdx.z == 0) { e = e1; sw = sw1; bw = bw1; eb = eb1; sb = sb1; bbv = bb1; dstW = dstW1; dstB = dstB1; }
    else                 { e = e2; sw = sw2; bw = bw2; eb = eb2; sb = sb2; bbv = bb2; dstW = dstW2; dstB = dstB2; }

    __shared__ float w2s[32 * 132];
    __shared__ float es [128 * 33];
    int r0 = blockIdx.y * 32;
    int c0 = blockIdx.x * 32;
    int tid = threadIdx.x;

#pragma unroll
    for (int i = 0; i < 16; i++) {
        int idx = tid + i * 256;
        int rr = idx >> 7, k = idx & 127;
        int r = r0 + rr;
        float v = (r < 128) ? sw[r * 128 + k] : bw[(r - 128) * 256 + 128 + k];
        w2s[rr * 132 + k] = v;
    }
#pragma unroll
    for (int i = 0; i < 16; i++) {
        int idx = tid + i * 256;
        int k = idx >> 5, cc = idx & 31;
        int c = c0 + cc;
        float v = 0.f;
        if (c < AUXC)      v = e[k * AUXC + c];
        else if (c == 319) v = eb[k];
        es[k * 33 + cc] = v;
    }
    __syncthreads();

    int tr = (tid >> 4) * 2;
    int tc = (tid & 15) * 2;
    float a00 = 0.f, a01 = 0.f, a10 = 0.f, a11 = 0.f;
#pragma unroll 8
    for (int k = 0; k < 128; k++) {
        float b0 = es[k * 33 + tc];
        float b1 = es[k * 33 + tc + 1];
        float w0 = w2s[tr * 132 + k];
        float w1 = w2s[(tr + 1) * 132 + k];
        a00 = fmaf(w0, b0, a00); a01 = fmaf(w0, b1, a01);
        a10 = fmaf(w1, b0, a10); a11 = fmaf(w1, b1, a11);
    }

    float vv[2][2] = {{a00, a01}, {a10, a11}};
#pragma unroll
    for (int i = 0; i < 2; i++) {
        int r = r0 + tr + i;
#pragma unroll
        for (int j = 0; j < 2; j++) {
            int c = c0 + tc + j;
            float v = vv[i][j];
            if (c == 319) {
                dstB[r] = v + ((r < 128) ? sb[r] : bbv[r - 128]);
                dstW[(long)r * 320 + c] = __float2half_rn(0.f);
            } else {
                dstW[(long)r * 320 + c] = __float2half_rn(v);
            }
        }
    }
}

// ================= concat aux =================
__global__ void __launch_bounds__(256)
concat_aux_kernel(const float* __restrict__ edge, const float* __restrict__ seg,
                  const float* __restrict__ pe,   const float* __restrict__ ps) {
    int b = blockIdx.z;
    int c = blockIdx.y;
    int p0 = blockIdx.x * 2048 + threadIdx.x * 8;
    half* dst = g_auxh + ((long)b * AUXK + c) * HW + p0;
    half h[8];
    if (c < AUXC) {
        const float* src;
        if (c < 128)       src = edge + ((long)b * 128 + c) * HW;
        else if (c < 256)  src = seg  + ((long)b * 128 + (c - 128)) * HW;
        else if (c == 256) src = pe   + (long)b * HW;
        else               src = ps   + ((long)b * 20 + (c - 257)) * HW;
        float4 v0 = *(const float4*)(src + p0);
        float4 v1 = *(const float4*)(src + p0 + 4);
        h[0] = __float2half_rn(v0.x); h[1] = __float2half_rn(v0.y);
        h[2] = __float2half_rn(v0.z); h[3] = __float2half_rn(v0.w);
        h[4] = __float2half_rn(v1.x); h[5] = __float2half_rn(v1.y);
        h[6] = __float2half_rn(v1.z); h[7] = __float2half_rn(v1.w);
    } else {
#pragma unroll
        for (int j = 0; j < 8; j++) h[j] = __ushort_as_half((unsigned short)0);
    }
    *(uint4*)dst = *(uint4*)h;
}

__global__ void __launch_bounds__(256)
cvt_f2h_kernel(const float* __restrict__ src, half* __restrict__ dst, long n) {
    long i = ((long)blockIdx.x * 256 + threadIdx.x) * 8;
    if (i >= n) return;
    float4 v0 = *(const float4*)(src + i);
    float4 v1 = *(const float4*)(src + i + 4);
    half h[8];
    h[0] = __float2half_rn(v0.x); h[1] = __float2half_rn(v0.y);
    h[2] = __float2half_rn(v0.z); h[3] = __float2half_rn(v0.w);
    h[4] = __float2half_rn(v1.x); h[5] = __float2half_rn(v1.y);
    h[6] = __float2half_rn(v1.z); h[7] = __float2half_rn(v1.w);
    *(uint4*)(dst + i) = *(uint4*)h;
}

// ================= LN finalize =================
__global__ void ln_final_kernel() {
    int b = blockIdx.x;
    if (threadIdx.x == 0) {
        float s = g_acc[2 * b], q = g_acc[2 * b + 1];
        float mu = s / (float)CHW;
        float var = q / (float)CHW - mu * mu;
        g_stats[2 * b]     = mu;
        g_stats[2 * b + 1] = rsqrtf(var + 1e-5f);
    }
}

// ================= merged softmax for s1 + s2 (half in/out) =================
__global__ void __launch_bounds__(256)
softmax_both_kernel(half* __restrict__ S1, half* __restrict__ S2) {
    long bid = blockIdx.x;
    half* p;
    int L, VPT;
    if (bid < (long)NB * 1024) {
        p = S1 + bid * 1024;
        L = 1024; VPT = 4;
    } else {
        p = S2 + (bid - (long)NB * 1024) * 256;
        L = 256; VPT = 1;
    }
    half* o = p;
    int tid = threadIdx.x;
    __shared__ float sh[8];
    float v[4];
    if (VPT == 4) {
        uint2 d = ((const uint2*)p)[tid];
        half2 h0 = *(half2*)&d.x, h1 = *(half2*)&d.y;
        v[0] = __low2float(h0); v[1] = __high2float(h0);
        v[2] = __low2float(h1); v[3] = __high2float(h1);
    } else {
        v[0] = __half2float(p[tid]);
    }

    float mx = -3.4e38f;
    for (int i = 0; i < VPT; i++) mx = fmaxf(mx, v[i]);
#pragma unroll
    for (int og = 16; og; og >>= 1) mx = fmaxf(mx, __shfl_xor_sync(0xffffffffu, mx, og));
    if ((tid & 31) == 0) sh[tid >> 5] = mx;
    __syncthreads();
    if (tid < 8) {
        float t = sh[tid];
#pragma unroll
        for (int og = 4; og; og >>= 1) t = fmaxf(t, __shfl_xor_sync(0xffu, t, og));
        if (tid == 0) sh[0] = t;
    }
    __syncthreads();
    mx = sh[0];
    __syncthreads();

    float s = 0.f;
    for (int i = 0; i < VPT; i++) { v[i] = __expf(v[i] - mx); s += v[i]; }
#pragma unroll
    for (int og = 16; og; og >>= 1) s += __shfl_xor_sync(0xffffffffu, s, og);
    if ((tid & 31) == 0) sh[tid >> 5] = s;
    __syncthreads();
    if (tid < 8) {
        float t = sh[tid];
#pragma unroll
        for (int og = 4; og; og >>= 1) t += __shfl_xor_sync(0xffu, t, og);
        if (tid == 0) sh[0] = t;
    }
    __syncthreads();
    float inv = 1.f / sh[0];
    if (VPT == 4) {
        half2 h0 = __floats2half2_rn(v[0] * inv, v[1] * inv);
        half2 h1 = __floats2half2_rn(v[2] * inv, v[3] * inv);
        uint2 d; d.x = *(uint32_t*)&h0; d.y = *(uint32_t*)&h1;
        ((uint2*)o)[tid] = d;
    } else {
        o[tid] = __float2half_rn(v[0] * inv);
    }
}

// ================= host =================
static void rung(bool transb, bool conv, int nT, int mT, int zT, const GP& g) {
    dim3 grid(nT, mT, zT);
    if (conv)        hgemm15<false, true ><<<grid, 256, GSM_BYTES>>>(g);
    else if (transb) hgemm15<true,  false><<<grid, 256, GSM_BYTES>>>(g);
    else             hgemm15<false, false><<<grid, 256, GSM_BYTES>>>(g);
}

extern "C" void kernel_launch(void* const* d_in, const int* in_sizes, int n_in,
                              void* d_out, int out_size) {
    const float* x    = (const float*)d_in[0];
    const float* edge = (const float*)d_in[1];
    const float* seg  = (const float*)d_in[2];
    const float* pe   = (const float*)d_in[3];
    const float* ps   = (const float*)d_in[4];
    const float* q_w  = (const float*)d_in[5];
    const float* q_b  = (const float*)d_in[6];
    const float* k_w  = (const float*)d_in[7];
    const float* k_b  = (const float*)d_in[8];
    const float* v_w  = (const float*)d_in[9];
    const float* v_b  = (const float*)d_in[10];
    const float* d1_embed_w = (const float*)d_in[11];
    const float* d1_embed_b = (const float*)d_in[12];
    const float* d1_scale_w = (const float*)d_in[13];
    const float* d1_scale_b = (const float*)d_in[14];
    const float* d1_bias_w  = (const float*)d_in[15];
    const float* d1_bias_b  = (const float*)d_in[16];
    const float* d2_embed_w = (const float*)d_in[17];
    const float* d2_embed_b = (const float*)d_in[18];
    const float* d2_scale_w = (const float*)d_in[19];
    const float* d2_scale_b = (const float*)d_in[20];
    const float* d2_bias_w  = (const float*)d_in[21];
    const float* d2_bias_b  = (const float*)d_in[22];
    const float* sc_w  = (const float*)d_in[23];
    const float* sc_b  = (const float*)d_in[24];
    const float* bi1_w = (const float*)d_in[25];
    const float* bi1_b = (const float*)d_in[26];
    const float* bi2_w = (const float*)d_in[27];
    const float* bi2_b = (const float*)d_in[28];
    float* out = (float*)d_out;

    cudaFuncSetAttribute(hgemm15<false, false>, cudaFuncAttributeMaxDynamicSharedMemorySize, GSM_BYTES);
    cudaFuncSetAttribute(hgemm15<true,  false>, cudaFuncAttributeMaxDynamicSharedMemorySize, GSM_BYTES);
    cudaFuncSetAttribute(hgemm15<false, true >, cudaFuncAttributeMaxDynamicSharedMemorySize, GSM_BYTES);

    half *wh, *auxh, *xh, *t0h, *gamh, *beth, *midh, *oh, *gfh, *tmph;
    half *qp1, *kp1, *vp1, *qp2, *kp2, *vp2, *s1h, *s2h;
    float *stats, *acc, *qkvb, *gbb1, *gbb2;
    cudaGetSymbolAddress((void**)&wh,   g_wh);
    cudaGetSymbolAddress((void**)&auxh, g_auxh);
    cudaGetSymbolAddress((void**)&xh,   g_xh);
    cudaGetSymbolAddress((void**)&t0h,  g_t0h);
    cudaGetSymbolAddress((void**)&gamh, g_gamh);
    cudaGetSymbolAddress((void**)&beth, g_beth);
    cudaGetSymbolAddress((void**)&midh, g_midh);
    cudaGetSymbolAddress((void**)&oh,   g_oh);
    cudaGetSymbolAddress((void**)&gfh,  g_gfh);
    cudaGetSymbolAddress((void**)&tmph, g_tmph);
    cudaGetSymbolAddress((void**)&qp1,  g_qp1);
    cudaGetSymbolAddress((void**)&kp1,  g_kp1);
    cudaGetSymbolAddress((void**)&vp1,  g_vp1);
    cudaGetSymbolAddress((void**)&qp2,  g_qp2);
    cudaGetSymbolAddress((void**)&kp2,  g_kp2);
    cudaGetSymbolAddress((void**)&vp2,  g_vp2);
    cudaGetSymbolAddress((void**)&s1h,  g_s1h);
    cudaGetSymbolAddress((void**)&s2h,  g_s2h);
    cudaGetSymbolAddress((void**)&stats, g_stats);
    cudaGetSymbolAddress((void**)&acc,   g_acc);
    cudaGetSymbolAddress((void**)&qkvb, g_qkvb);
    cudaGetSymbolAddress((void**)&gbb1, g_gbb1);
    cudaGetSymbolAddress((void**)&gbb2, g_gbb2);

    // 0. conversions / packing / weight fusion
    wconv_kernel<<<(W_TOTAL + 384 + 255) / 256, 256>>>(q_w, k_w, v_w, d1_bias_w, d2_bias_w,
                                                       sc_w, bi1_w, bi2_w, q_b, k_b, v_b);
    fuse_gb_kernel<<<dim3(10, 8, 2), 256>>>(d1_embed_w, d1_scale_w, d1_bias_w,
                                            d1_embed_b, d1_scale_b, d1_bias_b,
                                            d2_embed_w, d2_scale_w, d2_bias_w,
                                            d2_embed_b, d2_scale_b, d2_bias_b,
                                            wh + WO_GB1, gbb1, wh + WO_GB2, gbb2);
    cvt_f2h_kernel<<<(int)(((long)NB * CHW / 8 + 255) / 256), 256>>>(x, xh, (long)NB * CHW);
    concat_aux_kernel<<<dim3(2, AUXK, NB), 256>>>(edge, seg, pe, ps);

    // 1. merged: QKV conv1x1 (primary, fused LN stats) + ADN-1 gamma/betaS (secondary)
    cudaMemsetAsync(acc, 0, 96 * sizeof(float));
    {
        GP p = {};
        // primary: QKV
        p.A = wh + WO_QKV; p.lda = 128; p.sA = 0;
        p.B = xh; p.ldb = HW; p.sB = CHW;
        p.N = HW; p.sC = 3L * CHW; p.nkt = 2; p.mode = EP_LIN; p.lng = 1;
        p.bias = qkvb; p.ohh = t0h; p.acc = acc; p.mT1 = 3;
        // secondary: GB1
        p.A2g = wh + WO_GB1; p.lda2 = AUXK; p.sA2 = 0;
        p.B2g = auxh; p.ldb2 = HW; p.sB2 = (long)AUXK * HW;
        p.N2 = HW; p.nkt2 = AUXK / 64; p.sC2 = CHW;
        p.mode2 = EP_GB; p.bias2 = gbb1; p.out2 = gamh; p.ohh2 = beth;
        rung(false, false, 96 + 64, 1, NB, p);
    }
    ln_final_kernel<<<48, 32>>>();

    // 2. ADN-apply merged (48 z), fused patched writes
    {
        GP p = {};
        p.A = wh + WO_B1; p.lda = 256; p.sA = 0;
        p.B = t0h; p.ldb = HW; p.sB = CHW;
        p.N = HW; p.sC = CHW; p.nkt = 2; p.mode = EP_QKV3;
        p.t0h = t0h; p.gamh = gamh; p.beth = beth; p.stats = stats;
        p.d1q = qp1; p.d1k = kp1; p.d1v = vp1;
        p.d2q = qp2; p.d2k = kp2; p.d2v = vp2;
        rung(false, false, 32, 1, 48, p);
    }

    // 3. attention scores merged: score1 (y 0..7) + score2 (y == 8)
    {
        GP p = {};
        p.A = qp1; p.lda = 256; p.sA = 1024L * 256;
        p.B = kp1; p.ldb = 256; p.sB = 1024L * 256;
        p.N = 1024; p.sC = 1024L * 1024; p.nkt = 4; p.mode = EP_SCORE; p.scale = 0.0625f;
        p.ohh = s1h;
        p.A2g = qp2; p.lda2 = 1024; p.sA2 = 256L * 1024;
        p.B2g = kp2; p.ldb2 = 1024; p.sB2 = 256L * 1024;
        p.N2 = 256; p.nkt2 = 16; p.mT2 = 2; p.sC2 = 256L * 256;
        p.scale2 = 0.03125f; p.out2 = s2h;
        rung(true, false, 8, 9, NB, p);
    }
    softmax_both_kernel<<<NB * 1024 + NB * 256, 256>>>(s1h, s2h);

    // 4. merged PV1 (primary) + PV2 (secondary), fused LN stats for mid
    cudaMemsetAsync(acc, 0, 32 * sizeof(float));
    {
        GP p = {};
        // primary PV1: 8 m-tiles x 2 n-tiles
        p.A = s1h; p.lda = 1024; p.sA = 1024L * 1024;
        p.B = vp1; p.ldb = 256; p.sB = 1024L * 256;
        p.N = 256; p.sC = CHW; p.nkt = 16; p.mode = EP_PV1; p.lng = 2;
        p.xres = x; p.ohh = midh; p.acc = acc; p.mT1 = 8;
        // secondary PV2: 2 m-tiles x 8 n-tiles
        p.A2g = s2h; p.lda2 = 256; p.sA2 = 256L * 256;
        p.B2g = vp2; p.ldb2 = 1024; p.sB2 = 256L * 1024;
        p.N2 = 1024; p.nkt2 = 4; p.sC2 = CHW;
        p.mode2 = EP_PV2; p.out2 = midh;
        rung(false, false, 16 + 16, 1, NB, p);
    }
    ln_final_kernel<<<16, 32>>>();

    // 5. ADN-2: gamma/betaS from aux (fused), then apply
    {
        GP p = {};
        p.A = wh + WO_GB2; p.lda = AUXK; p.sA = 0;
        p.B = auxh; p.ldb = HW; p.sB = (long)AUXK * HW;
        p.N = HW; p.sC = CHW; p.nkt = AUXK / 64; p.mode = EP_GB;
        p.bias = gbb2; p.ohh = gamh; p.ohh2 = beth;
        rung(false, false, 32, 2, NB, p);
    }
    {
        GP p = {};
        p.A = wh + WO_B2; p.lda = 256; p.sA = 0;
        p.B = midh; p.ldb = HW; p.sB = CHW;
        p.N = HW; p.sC = CHW; p.nkt = 2; p.mode = EP_ADN;
        p.t0h = midh; p.gamh = gamh; p.beth = beth; p.stats = stats;
        p.ohh = oh;
        rung(false, false, 32, 1, NB, p);
    }

    // 6. conv3x3 chain: sc+bi1 merged, then final
    {
        GP p = {};
        p.A = wh + WO_SC; p.lda = 1152; p.sA = 0;
        p.B = oh; p.ldb = 0; p.sB = CHW;
        p.N = HW; p.sC = CHW; p.nkt = 18;
        p.mode = EP_TANH; p.dil = 1; p.bias = sc_b; p.ohh = gfh;
        p.A2 = wh + WO_BI1; p.mode2c = EP_GELU; p.dil2 = 2; p.bias2c = bi1_b; p.ohh2 = tmph;
        rung(false, true, 32, 2, NB, p);
    }
    {
        GP p = {};
        p.A = wh + WO_BI2; p.lda = 1152; p.sA = 0;
        p.B = tmph; p.ldb = 0; p.sB = CHW;
        p.N = HW; p.sC = CHW; p.nkt = 18; p.mode = EP_FINAL; p.dil = 1;
        p.bias = bi2_b; p.midh = midh; p.gfh = gfh; p.of = out;
        rung(false, true, 32, 1, NB, p);
    }
}

// round 16
// speedup vs baseline: 1.0885x; 1.0885x over previous
#include <cuda_runtime.h>
#include <cuda_fp16.h>
#include <math.h>
#include <stdint.h>

// ---------------- problem constants ----------------
#define NB 16
#define HW 4096
#define CHW (128*HW)          // 524288
#define AUXC 277
#define AUXK 320

// ---------------- weight pack offsets (halfs) ----------------
#define WO_QKV  0             // [384][128]
#define WO_GB1  49152         // [256][320]  fused (S|Bh)·E
#define WO_B1   131072        // [128][256]
#define WO_GB2  163840        // [256][320]
#define WO_B2   245760        // [128][256]
#define WO_SC   278528        // [128][1152] plane-major
#define WO_BI1  425984
#define WO_BI2  573440
#define W_TOTAL 720896

// ---------------- scratch ----------------
__device__ __align__(256) half  g_wh  [W_TOTAL];
__device__ float g_qkvb[384];
__device__ float g_gbb1[256];
__device__ float g_gbb2[256];
__device__ __align__(256) half  g_auxh[(long)NB*AUXK*HW];
__device__ __align__(256) half  g_xh  [(long)NB*CHW];
__device__ __align__(256) half  g_t0h [(long)NB*3*CHW];
__device__ __align__(256) half  g_gamh[(long)NB*CHW];
__device__ __align__(256) half  g_beth[(long)NB*CHW];
__device__ __align__(256) half  g_midh[(long)NB*CHW];
__device__ __align__(256) half  g_oh  [(long)NB*CHW];
__device__ __align__(256) half  g_gfh [(long)NB*CHW];
__device__ __align__(256) half  g_tmph[(long)NB*CHW];
__device__ __align__(256) half  g_qp1 [NB*1024L*256];
__device__ __align__(256) half  g_kp1 [NB*1024L*256];
__device__ __align__(256) half  g_vp1 [NB*1024L*256];
__device__ __align__(256) half  g_qp2 [NB*256L*1024];
__device__ __align__(256) half  g_kp2 [NB*256L*1024];
__device__ __align__(256) half  g_vp2 [NB*256L*1024];
__device__ __align__(256) half  g_s1h [NB*1024L*1024];
__device__ __align__(256) half  g_s2h [NB*256L*256];
__device__ float g_stats[96];
__device__ float g_acc  [96];

// ---------------- epilogue modes ----------------
#define EP_LIN   0
#define EP_GB    1
#define EP_QKV3  2
#define EP_ADN   3
#define EP_SCORE 4
#define EP_PV1   5
#define EP_PV2   6
#define EP_TANH  7
#define EP_GELU  8
#define EP_FINAL 9

// ---------------- smem geometry (halfs), Kt = 64 ----------------
#define A_LDH 72
#define A_ROWB 144
#define BK_LDH 136
#define BK_ROWB 272
#define STAGE_HALFS 18432
#define STAGE_BYTES 36864
#define B_OFF_H 9216
#define GSM_BYTES (2*STAGE_BYTES)

// ---------------- asm helpers ----------------
__device__ __forceinline__ uint32_t smem_u32(const void* p) {
    uint32_t a;
    asm("{ .reg .u64 t; cvta.to.shared.u64 t, %1; cvt.u32.u64 %0, t; }" : "=r"(a) : "l"(p));
    return a;
}
__device__ __forceinline__ void ldsm_x4(uint32_t* r, uint32_t addr) {
    asm volatile("ldmatrix.sync.aligned.m8n8.x4.shared.b16 {%0,%1,%2,%3}, [%4];"
                 : "=r"(r[0]), "=r"(r[1]), "=r"(r[2]), "=r"(r[3]) : "r"(addr));
}
__device__ __forceinline__ void ldsm_x4t(uint32_t* r, uint32_t addr) {
    asm volatile("ldmatrix.sync.aligned.m8n8.x4.trans.shared.b16 {%0,%1,%2,%3}, [%4];"
                 : "=r"(r[0]), "=r"(r[1]), "=r"(r[2]), "=r"(r[3]) : "r"(addr));
}
__device__ __forceinline__ void mma_f16(float* c,
                                        uint32_t a0, uint32_t a1, uint32_t a2, uint32_t a3,
                                        uint32_t b0, uint32_t b1) {
    asm volatile(
        "mma.sync.aligned.m16n8k16.row.col.f32.f16.f16.f32 "
        "{%0,%1,%2,%3}, {%4,%5,%6,%7}, {%8,%9}, {%0,%1,%2,%3};"
        : "+f"(c[0]), "+f"(c[1]), "+f"(c[2]), "+f"(c[3])
        : "r"(a0), "r"(a1), "r"(a2), "r"(a3), "r"(b0), "r"(b1));
}

// ---------------- GEMM params ----------------
struct GP {
    const half* A; int lda; long sA;
    const half* B; int ldb; long sB;
    int N; long sC; int nkt;
    int mode; float scale; int dil; int lng;
    const float* bias;
    const half* t0h; const half* gamh; const half* beth; const float* stats;
    const float* xres; const half* midh; const half* gfh;
    float* of; half* ohh; half* ohh2;
    half* d1q; half* d1k; half* d1v;
    half* d2q; half* d2k; half* d2v;
    float* acc;
    // conv merged variant (blockIdx.y == 1)
    const half* A2; const float* bias2c; int dil2; int mode2c;
    // secondary GEMM (merged TRANSB score launch)
    const half* A2g; long sA2;
    const half* B2g; int ldb2; long sB2;
    int N2, nkt2, mT2, lda2;
    long sC2; float scale2; half* out2;
};

// ================= fp16 tensor-core GEMM, Kt=64 =================
template<bool TRANSB, bool CONV>
__global__ void __launch_bounds__(256)
hgemm16(GP g) {
    extern __shared__ __align__(16) half sm[];
    int bb = blockIdx.z;
    int n0 = blockIdx.x * 128;
    int m0 = CONV ? 0 : blockIdx.y * 128;

    const half* Aw = g.A;
    const half* Bw = g.B;
    int lda = g.lda, ldb = g.ldb;
    long sA = g.sA, sB = g.sB, sC = g.sC;
    int NN = g.N, nkt = g.nkt;
    int dil = g.dil;
    int mode = g.mode;
    float scale = g.scale;
    const float* biasL = g.bias;
    half* ohhL = g.ohh;

    if (CONV && blockIdx.y == 1) {
        Aw = g.A2; dil = g.dil2; mode = g.mode2c; biasL = g.bias2c; ohhL = g.ohh2;
    }
    if (TRANSB && g.N2 && blockIdx.y == gridDim.y - 1) {
        int t2x = g.N2 >> 7;
        int id = blockIdx.x;
        if (id >= g.mT2 * t2x) return;
        m0 = (id / t2x) * 128;
        n0 = (id % t2x) * 128;
        Aw = g.A2g; Bw = g.B2g;
        lda = g.lda2; ldb = g.ldb2;
        sA = g.sA2; sB = g.sB2; sC = g.sC2;
        NN = g.N2; nkt = g.nkt2; scale = g.scale2;
        ohhL = g.out2;
    }
    const half* Ap = Aw + (long)bb * sA;
    const half* Bp = Bw + (long)bb * sB;

    int tid  = threadIdx.x;
    int lane = tid & 31;
    int warp = tid >> 5;
    int wm = (warp >> 2) * 64;
    int wn = (warp & 3) * 32;

    int arow  = tid >> 1;
    int akseg = (tid & 1) * 32;
    int bkr = tid >> 2;
    int bns = (tid & 3) * 32;
    int cn    = tid & 127;
    int ckseg = (tid >> 7) * 32;

    uint32_t sbase = smem_u32(sm);
    int rowsel = lane & 15;
    int colsel = (lane >> 4) * 16;

    uint4 ra[4], rb[4];
    float acc[4][4][4] = {};

    for (int it = 0; it <= nkt; it++) {
        if (it < nkt) {
            int kt = it * 64;
            const half* ar = Ap + (long)(m0 + arow) * lda + kt + akseg;
#pragma unroll
            for (int j = 0; j < 4; j++) ra[j] = *(const uint4*)(ar + j * 8);
            if (CONV) {
                int tap = kt >> 7;
                int cb  = (kt & 127) + ckseg;
                int dy = (tap / 3 - 1) * dil;
                int dx = (tap % 3 - 1) * dil;
                int p = n0 + cn;
                int h = (p >> 6) + dy;
                int w = (p & 63) + dx;
                half rc[32];
                if ((unsigned)h < 64u && (unsigned)w < 64u) {
                    const half* base = Bp + (long)cb * HW + h * 64 + w;
#pragma unroll
                    for (int j = 0; j < 32; j++) rc[j] = base[(long)j * HW];
                } else {
#pragma unroll
                    for (int j = 0; j < 32; j++) rc[j] = __ushort_as_half((unsigned short)0);
                }
#pragma unroll
                for (int j = 0; j < 4; j++) rb[j] = ((uint4*)rc)[j];
            } else if (TRANSB) {
                const half* br = Bp + (long)(n0 + arow) * ldb + kt + akseg;
#pragma unroll
                for (int j = 0; j < 4; j++) rb[j] = *(const uint4*)(br + j * 8);
            } else {
                const half* br = Bp + (long)(kt + bkr) * ldb + n0 + bns;
#pragma unroll
                for (int j = 0; j < 4; j++) rb[j] = *(const uint4*)(br + j * 8);
            }
        }

        if (it > 0) {
            uint32_t stA = sbase + (uint32_t)(((it - 1) & 1) * STAGE_BYTES);
            uint32_t stB = stA + B_OFF_H * 2;
            uint32_t abase = stA + (uint32_t)(wm + rowsel) * A_ROWB + colsel;
#pragma unroll
            for (int ks = 0; ks < 4; ks++) {
                uint32_t af[4][4];
#pragma unroll
                for (int mt = 0; mt < 4; mt++)
                    ldsm_x4(af[mt], abase + mt * 16 * A_ROWB + ks * 32);
                uint32_t bf[2][4];
                if (TRANSB || CONV) {
                    uint32_t bbase = stB + (uint32_t)(wn + rowsel) * A_ROWB + colsel;
#pragma unroll
                    for (int ntp = 0; ntp < 2; ntp++)
                        ldsm_x4(bf[ntp], bbase + ntp * 16 * A_ROWB + ks * 32);
                } else {
                    uint32_t bbase = stB + (uint32_t)(ks * 16 + rowsel) * BK_ROWB
                                   + (uint32_t)(wn + (lane >> 4) * 8) * 2;
#pragma unroll
                    for (int ntp = 0; ntp < 2; ntp++)
                        ldsm_x4t(bf[ntp], bbase + ntp * 32);
                }
#pragma unroll
                for (int mt = 0; mt < 4; mt++) {
#pragma unroll
                    for (int nt = 0; nt < 4; nt++) {
                        int ntp = nt >> 1, par = nt & 1;
                        uint32_t b0, b1;
                        if (TRANSB || CONV) { b0 = bf[ntp][par];     b1 = bf[ntp][par + 2]; }
                        else                { b0 = bf[ntp][par * 2]; b1 = bf[ntp][par * 2 + 1]; }
                        mma_f16(acc[mt][nt],
                                af[mt][0], af[mt][1], af[mt][2], af[mt][3], b0, b1);
                    }
                }
            }
        }

        if (it < nkt) {
            half* stA = sm + (it & 1) * STAGE_HALFS;
            half* stB = stA + B_OFF_H;
            half* da = stA + arow * A_LDH + akseg;
#pragma unroll
            for (int j = 0; j < 4; j++) *(uint4*)(da + j * 8) = ra[j];
            half* db;
            if (CONV)        db = stB + cn * A_LDH + ckseg;
            else if (TRANSB) db = stB + arow * A_LDH + akseg;
            else             db = stB + bkr * BK_LDH + bns;
#pragma unroll
            for (int j = 0; j < 4; j++) *(uint4*)(db + j * 8) = rb[j];
        }
        __syncthreads();
    }

    // ---- epilogue (pair-vectorized: n is always even) ----
    int r  = lane >> 2;
    int cg = lane & 3;
    long bbC = (long)bb * sC;
    float mu = 0.f, rs = 0.f;
    if (mode == EP_QKV3 || mode == EP_ADN) { mu = g.stats[2 * bb]; rs = g.stats[2 * bb + 1]; }
    int b3 = bb / 3, t3 = bb - 3 * (bb / 3);
    float lsum = 0.f, lsq = 0.f;

    auto emit2 = [&](float v0, float v1, int m, int n) {
        long li = (long)m * NN + n;
        if (mode == EP_LIN) {
            float r0 = v0 + biasL[m], r1 = v1 + biasL[m];
            if (g.lng) { lsum += r0 + r1; lsq += r0 * r0 + r1 * r1; }
            *(half2*)(ohhL + bbC + li) = __floats2half2_rn(r0, r1);
        } else if (mode == EP_GB) {
            float r0 = v0 + biasL[m], r1 = v1 + biasL[m];
            long o = (long)bb * CHW + (long)(m & 127) * HW + n;
            half2 hv = __floats2half2_rn(r0, r1);
            if (m < 128) *(half2*)(ohhL + o) = hv;
            else         *(half2*)(g.ohh2 + o) = hv;
        } else if (mode == EP_QKV3) {
            long ti = bbC + li;
            long gi = (long)b3 * CHW + li;
            half2 tp = *(const half2*)(g.t0h + ti);
            half2 gp = *(const half2*)(g.gamh + gi);
            half2 bp = *(const half2*)(g.beth + gi);
            float val0 = (__low2float(tp)  - mu) * rs * __low2float(gp)  + v0 + __low2float(bp);
            float val1 = (__high2float(tp) - mu) * rs * __high2float(gp) + v1 + __high2float(bp);
            half2 hv = __floats2half2_rn(val0, val1);
            int h = n >> 6, w = n & 63;
            if (m < 64) {
                int tk = (h >> 1) * 32 + (w >> 1);
                int d  = m * 4 + (h & 1) * 2;
                half* dst = (t3 == 0) ? g.d1q : (t3 == 1) ? g.d1k : g.d1v;
                *(half2*)(dst + (long)b3 * (1024L * 256) + (long)tk * 256 + d) = hv;
            } else {
                int tk = (h >> 2) * 16 + (w >> 2);
                int d  = (m - 64) * 16 + (h & 3) * 4 + (w & 3);
                half* dst = (t3 == 0) ? g.d2q : (t3 == 1) ? g.d2k : g.d2v;
                *(half2*)(dst + (long)b3 * (256L * 1024) + (long)tk * 1024 + d) = hv;
            }
        } else if (mode == EP_ADN) {
            long gi = bbC + li;
            half2 tp = *(const half2*)(g.t0h + gi);
            half2 gp = *(const half2*)(g.gamh + gi);
            half2 bp = *(const half2*)(g.beth + gi);
            float r0 = (__low2float(tp)  - mu) * rs * __low2float(gp)  + v0 + __low2float(bp);
            float r1 = (__high2float(tp) - mu) * rs * __high2float(gp) + v1 + __high2float(bp);
            *(half2*)(ohhL + gi) = __floats2half2_rn(r0, r1);
        } else if (mode == EP_SCORE) {
            *(half2*)(ohhL + bbC + li) = __floats2half2_rn(v0 * scale, v1 * scale);
        } else if (mode == EP_PV1) {
            int c  = n >> 2;
            int py = (n >> 1) & 1;
            int h = (m >> 5) * 2 + py, w = (m & 31) * 2;
            long tgt = bbC + (long)c * HW + h * 64 + w;
            float2 xr = *(const float2*)(g.xres + tgt);
            float r0 = xr.x + v0, r1 = xr.y + v1;
            lsum += r0 + r1; lsq += r0 * r0 + r1 * r1;
            *(half2*)(ohhL + tgt) = __floats2half2_rn(r0, r1);
        } else if (mode == EP_PV2) {
            int c  = 64 + (n >> 4);
            int py = (n >> 2) & 3, px = n & 3;
            int h = (m >> 4) * 4 + py, w = (m & 15) * 4 + px;
            long tgt = bbC + (long)c * HW + h * 64 + w;
            float2 xr = *(const float2*)(g.xres + tgt);
            float r0 = xr.x + v0, r1 = xr.y + v1;
            lsum += r0 + r1; lsq += r0 * r0 + r1 * r1;
            *(half2*)(ohhL + tgt) = __floats2half2_rn(r0, r1);
        } else if (mode == EP_TANH) {
            *(half2*)(ohhL + bbC + li) =
                __floats2half2_rn(tanhf(v0 + biasL[m]), tanhf(v1 + biasL[m]));
        } else if (mode == EP_GELU) {
            float u0 = v0 + biasL[m], u1 = v1 + biasL[m];
            float r0 = 0.5f * u0 * (1.f + erff(u0 * 0.70710678118654752f));
            float r1 = 0.5f * u1 * (1.f + erff(u1 * 0.70710678118654752f));
            *(half2*)(ohhL + bbC + li) = __floats2half2_rn(r0, r1);
        } else { // EP_FINAL
            long gi = bbC + li;
            half2 mh = *(const half2*)(g.midh + gi);
            half2 gh = *(const half2*)(g.gfh + gi);
            float2 o;
            o.x = __low2float(mh)  * __low2float(gh)  + v0 + biasL[m];
            o.y = __high2float(mh) * __high2float(gh) + v1 + biasL[m];
            *(float2*)(g.of + gi) = o;
        }
    };

#pragma unroll
    for (int mt = 0; mt < 4; mt++) {
#pragma unroll
        for (int nt = 0; nt < 4; nt++) {
            int m1 = m0 + wm + mt * 16 + r;
            int nn = n0 + wn + nt * 8 + cg * 2;
            emit2(acc[mt][nt][0], acc[mt][nt][1], m1, nn);
            emit2(acc[mt][nt][2], acc[mt][nt][3], m1 + 8, nn);
        }
    }

    // ---- fused LN partial-stats reduction ----
    if (g.lng) {
#pragma unroll
        for (int o = 16; o; o >>= 1) {
            lsum += __shfl_xor_sync(0xffffffffu, lsum, o);
            lsq  += __shfl_xor_sync(0xffffffffu, lsq,  o);
        }
        float* smf = (float*)sm;
        if (lane == 0) { smf[warp * 2] = lsum; smf[warp * 2 + 1] = lsq; }
        __syncthreads();
        if (warp == 0 && lane < 8) {
            lsum = smf[lane * 2]; lsq = smf[lane * 2 + 1];
#pragma unroll
            for (int o = 4; o; o >>= 1) {
                lsum += __shfl_xor_sync(0xffu, lsum, o);
                lsq  += __shfl_xor_sync(0xffu, lsq,  o);
            }
            if (lane == 0) {
                int grp = (g.lng == 1) ? bb * 3 + (m0 >> 7) : bb;
                atomicAdd(&g.acc[2 * grp],     lsum);
                atomicAdd(&g.acc[2 * grp + 1], lsq);
            }
        }
    }
}

// ================= weight repack + bias pack =================
__global__ void __launch_bounds__(256)
wconv_kernel(const float* qw, const float* kw, const float* vw,
             const float* b1, const float* b2,
             const float* sc, const float* bi1, const float* bi2,
             const float* qb, const float* kb, const float* vb) {
    int i = blockIdx.x * 256 + threadIdx.x;
    if (i >= W_TOTAL) {
        int j = i - W_TOTAL;
        if (j < 384) g_qkvb[j] = j < 128 ? qb[j] : j < 256 ? kb[j - 128] : vb[j - 256];
        return;
    }
    float v;
    if (i < WO_GB1) {
        int t = i >> 14, j = i & 16383;
        v = (t == 0 ? qw : t == 1 ? kw : vw)[j];
    } else if (i < WO_B1) {
        return;
    } else if (i < WO_GB2) {
        v = b1[i - WO_B1];
    } else if (i < WO_B2) {
        return;
    } else if (i < WO_SC) {
        v = b2[i - WO_B2];
    } else {
        int j = i - WO_SC;
        int blk = j / 147456, t = j % 147456;
        int o = t / 1152, rr = t % 1152;
        int tap = rr >> 7, c = rr & 127;
        const float* w = (blk == 0 ? sc : blk == 1 ? bi1 : bi2);
        v = w[((o * 128 + c) * 3 + tap / 3) * 3 + (tap % 3)];
    }
    g_wh[i] = __float2half_rn(v);
}

// ================= tiled fuse, both ADN sets in one launch (grid.z) =================
__global__ void __launch_bounds__(256)
fuse_gb_kernel(const float* e1,  const float* sw1, const float* bw1,
               const float* eb1, const float* sb1, const float* bb1,
               const float* e2,  const float* sw2, const float* bw2,
               const float* eb2, const float* sb2, const float* bb2,
               half* dstW1, float* dstB1, half* dstW2, float* dstB2) {
    const float *e, *sw, *bw, *eb, *sb, *bbv;
    half* dstW; float* dstB;
    if (blockIdx.z == 0) { e = e1; sw = sw1; bw = bw1; eb = eb1; sb = sb1; bbv = bb1; dstW = dstW1; dstB = dstB1; }
    else                 { e = e2; sw = sw2; bw = bw2; eb = eb2; sb = sb2; bbv = bb2; dstW = dstW2; dstB = dstB2; }

    __shared__ float w2s[32 * 132];
    __shared__ float es [128 * 33];
    int r0 = blockIdx.y * 32;
    int c0 = blockIdx.x * 32;
    int tid = threadIdx.x;

#pragma unroll
    for (int i = 0; i < 16; i++) {
        int idx = tid + i * 256;
        int rr = idx >> 7, k = idx & 127;
        int r = r0 + rr;
        float v = (r < 128) ? sw[r * 128 + k] : bw[(r - 128) * 256 + 128 + k];
        w2s[rr * 132 + k] = v;
    }
#pragma unroll
    for (int i = 0; i < 16; i++) {
        int idx = tid + i * 256;
        int k = idx >> 5, cc = idx & 31;
        int c = c0 + cc;
        float v = 0.f;
        if (c < AUXC)      v = e[k * AUXC + c];
        else if (c == 319) v = eb[k];
        es[k * 33 + cc] = v;
    }
    __syncthreads();

    int tr = (tid >> 4) * 2;
    int tc = (tid & 15) * 2;
    float a00 = 0.f, a01 = 0.f, a10 = 0.f, a11 = 0.f;
#pragma unroll 8
    for (int k = 0; k < 128; k++) {
        float b0 = es[k * 33 + tc];
        float b1 = es[k * 33 + tc + 1];
        float w0 = w2s[tr * 132 + k];
        float w1 = w2s[(tr + 1) * 132 + k];
        a00 = fmaf(w0, b0, a00); a01 = fmaf(w0, b1, a01);
        a10 = fmaf(w1, b0, a10); a11 = fmaf(w1, b1, a11);
    }

    float vv[2][2] = {{a00, a01}, {a10, a11}};
#pragma unroll
    for (int i = 0; i < 2; i++) {
        int r = r0 + tr + i;
#pragma unroll
        for (int j = 0; j < 2; j++) {
            int c = c0 + tc + j;
            float v = vv[i][j];
            if (c == 319) {
                dstB[r] = v + ((r < 128) ? sb[r] : bbv[r - 128]);
                dstW[(long)r * 320 + c] = __float2half_rn(0.f);
            } else {
                dstW[(long)r * 320 + c] = __float2half_rn(v);
            }
        }
    }
}

// ================= concat aux =================
__global__ void __launch_bounds__(256)
concat_aux_kernel(const float* __restrict__ edge, const float* __restrict__ seg,
                  const float* __restrict__ pe,   const float* __restrict__ ps) {
    int b = blockIdx.z;
    int c = blockIdx.y;
    int p0 = blockIdx.x * 2048 + threadIdx.x * 8;
    half* dst = g_auxh + ((long)b * AUXK + c) * HW + p0;
    half h[8];
    if (c < AUXC) {
        const float* src;
        if (c < 128)       src = edge + ((long)b * 128 + c) * HW;
        else if (c < 256)  src = seg  + ((long)b * 128 + (c - 128)) * HW;
        else if (c == 256) src = pe   + (long)b * HW;
        else               src = ps   + ((long)b * 20 + (c - 257)) * HW;
        float4 v0 = *(const float4*)(src + p0);
        float4 v1 = *(const float4*)(src + p0 + 4);
        h[0] = __float2half_rn(v0.x); h[1] = __float2half_rn(v0.y);
        h[2] = __float2half_rn(v0.z); h[3] = __float2half_rn(v0.w);
        h[4] = __float2half_rn(v1.x); h[5] = __float2half_rn(v1.y);
        h[6] = __float2half_rn(v1.z); h[7] = __float2half_rn(v1.w);
    } else {
#pragma unroll
        for (int j = 0; j < 8; j++) h[j] = __ushort_as_half((unsigned short)0);
    }
    *(uint4*)dst = *(uint4*)h;
}

__global__ void __launch_bounds__(256)
cvt_f2h_kernel(const float* __restrict__ src, half* __restrict__ dst, long n) {
    long i = ((long)blockIdx.x * 256 + threadIdx.x) * 8;
    if (i >= n) return;
    float4 v0 = *(const float4*)(src + i);
    float4 v1 = *(const float4*)(src + i + 4);
    half h[8];
    h[0] = __float2half_rn(v0.x); h[1] = __float2half_rn(v0.y);
    h[2] = __float2half_rn(v0.z); h[3] = __float2half_rn(v0.w);
    h[4] = __float2half_rn(v1.x); h[5] = __float2half_rn(v1.y);
    h[6] = __float2half_rn(v1.z); h[7] = __float2half_rn(v1.w);
    *(uint4*)(dst + i) = *(uint4*)h;
}

// ================= LN finalize =================
__global__ void ln_final_kernel() {
    int b = blockIdx.x;
    if (threadIdx.x == 0) {
        float s = g_acc[2 * b], q = g_acc[2 * b + 1];
        float mu = s / (float)CHW;
        float var = q / (float)CHW - mu * mu;
        g_stats[2 * b]     = mu;
        g_stats[2 * b + 1] = rsqrtf(var + 1e-5f);
    }
}

// ================= merged softmax for s1 + s2 (half in/out) =================
__global__ void __launch_bounds__(256)
softmax_both_kernel(half* __restrict__ S1, half* __restrict__ S2) {
    long bid = blockIdx.x;
    half* p;
    int VPT;
    if (bid < (long)NB * 1024) {
        p = S1 + bid * 1024;
        VPT = 4;
    } else {
        p = S2 + (bid - (long)NB * 1024) * 256;
        VPT = 1;
    }
    half* o = p;
    int tid = threadIdx.x;
    __shared__ float sh[8];
    float v[4];
    if (VPT == 4) {
        uint2 d = ((const uint2*)p)[tid];
        half2 h0 = *(half2*)&d.x, h1 = *(half2*)&d.y;
        v[0] = __low2float(h0); v[1] = __high2float(h0);
        v[2] = __low2float(h1); v[3] = __high2float(h1);
    } else {
        v[0] = __half2float(p[tid]);
    }

    float mx = -3.4e38f;
    for (int i = 0; i < VPT; i++) mx = fmaxf(mx, v[i]);
#pragma unroll
    for (int og = 16; og; og >>= 1) mx = fmaxf(mx, __shfl_xor_sync(0xffffffffu, mx, og));
    if ((tid & 31) == 0) sh[tid >> 5] = mx;
    __syncthreads();
    if (tid < 8) {
        float t = sh[tid];
#pragma unroll
        for (int og = 4; og; og >>= 1) t = fmaxf(t, __shfl_xor_sync(0xffu, t, og));
        if (tid == 0) sh[0] = t;
    }
    __syncthreads();
    mx = sh[0];
    __syncthreads();

    float s = 0.f;
    for (int i = 0; i < VPT; i++) { v[i] = __expf(v[i] - mx); s += v[i]; }
#pragma unroll
    for (int og = 16; og; og >>= 1) s += __shfl_xor_sync(0xffffffffu, s, og);
    if ((tid & 31) == 0) sh[tid >> 5] = s;
    __syncthreads();
    if (tid < 8) {
        float t = sh[tid];
#pragma unroll
        for (int og = 4; og; og >>= 1) t += __shfl_xor_sync(0xffu, t, og);
        if (tid == 0) sh[0] = t;
    }
    __syncthreads();
    float inv = 1.f / sh[0];
    if (VPT == 4) {
        half2 h0 = __floats2half2_rn(v[0] * inv, v[1] * inv);
        half2 h1 = __floats2half2_rn(v[2] * inv, v[3] * inv);
        uint2 d; d.x = *(uint32_t*)&h0; d.y = *(uint32_t*)&h1;
        ((uint2*)o)[tid] = d;
    } else {
        o[tid] = __float2half_rn(v[0] * inv);
    }
}

// ================= host =================
static void rung(bool transb, bool conv, int nT, int mT, int zT, const GP& g) {
    dim3 grid(nT, mT, zT);
    if (conv)        hgemm16<false, true ><<<grid, 256, GSM_BYTES>>>(g);
    else if (transb) hgemm16<true,  false><<<grid, 256, GSM_BYTES>>>(g);
    else             hgemm16<false, false><<<grid, 256, GSM_BYTES>>>(g);
}

extern "C" void kernel_launch(void* const* d_in, const int* in_sizes, int n_in,
                              void* d_out, int out_size) {
    const float* x    = (const float*)d_in[0];
    const float* edge = (const float*)d_in[1];
    const float* seg  = (const float*)d_in[2];
    const float* pe   = (const float*)d_in[3];
    const float* ps   = (const float*)d_in[4];
    const float* q_w  = (const float*)d_in[5];
    const float* q_b  = (const float*)d_in[6];
    const float* k_w  = (const float*)d_in[7];
    const float* k_b  = (const float*)d_in[8];
    const float* v_w  = (const float*)d_in[9];
    const float* v_b  = (const float*)d_in[10];
    const float* d1_embed_w = (const float*)d_in[11];
    const float* d1_embed_b = (const float*)d_in[12];
    const float* d1_scale_w = (const float*)d_in[13];
    const float* d1_scale_b = (const float*)d_in[14];
    const float* d1_bias_w  = (const float*)d_in[15];
    const float* d1_bias_b  = (const float*)d_in[16];
    const float* d2_embed_w = (const float*)d_in[17];
    const float* d2_embed_b = (const float*)d_in[18];
    const float* d2_scale_w = (const float*)d_in[19];
    const float* d2_scale_b = (const float*)d_in[20];
    const float* d2_bias_w  = (const float*)d_in[21];
    const float* d2_bias_b  = (const float*)d_in[22];
    const float* sc_w  = (const float*)d_in[23];
    const float* sc_b  = (const float*)d_in[24];
    const float* bi1_w = (const float*)d_in[25];
    const float* bi1_b = (const float*)d_in[26];
    const float* bi2_w = (const float*)d_in[27];
    const float* bi2_b = (const float*)d_in[28];
    float* out = (float*)d_out;

    cudaFuncSetAttribute(hgemm16<false, false>, cudaFuncAttributeMaxDynamicSharedMemorySize, GSM_BYTES);
    cudaFuncSetAttribute(hgemm16<true,  false>, cudaFuncAttributeMaxDynamicSharedMemorySize, GSM_BYTES);
    cudaFuncSetAttribute(hgemm16<false, true >, cudaFuncAttributeMaxDynamicSharedMemorySize, GSM_BYTES);

    half *wh, *auxh, *xh, *t0h, *gamh, *beth, *midh, *oh, *gfh, *tmph;
    half *qp1, *kp1, *vp1, *qp2, *kp2, *vp2, *s1h, *s2h;
    float *stats, *acc, *qkvb, *gbb1, *gbb2;
    cudaGetSymbolAddress((void**)&wh,   g_wh);
    cudaGetSymbolAddress((void**)&auxh, g_auxh);
    cudaGetSymbolAddress((void**)&xh,   g_xh);
    cudaGetSymbolAddress((void**)&t0h,  g_t0h);
    cudaGetSymbolAddress((void**)&gamh, g_gamh);
    cudaGetSymbolAddress((void**)&beth, g_beth);
    cudaGetSymbolAddress((void**)&midh, g_midh);
    cudaGetSymbolAddress((void**)&oh,   g_oh);
    cudaGetSymbolAddress((void**)&gfh,  g_gfh);
    cudaGetSymbolAddress((void**)&tmph, g_tmph);
    cudaGetSymbolAddress((void**)&qp1,  g_qp1);
    cudaGetSymbolAddress((void**)&kp1,  g_kp1);
    cudaGetSymbolAddress((void**)&vp1,  g_vp1);
    cudaGetSymbolAddress((void**)&qp2,  g_qp2);
    cudaGetSymbolAddress((void**)&kp2,  g_kp2);
    cudaGetSymbolAddress((void**)&vp2,  g_vp2);
    cudaGetSymbolAddress((void**)&s1h,  g_s1h);
    cudaGetSymbolAddress((void**)&s2h,  g_s2h);
    cudaGetSymbolAddress((void**)&stats, g_stats);
    cudaGetSymbolAddress((void**)&acc,   g_acc);
    cudaGetSymbolAddress((void**)&qkvb, g_qkvb);
    cudaGetSymbolAddress((void**)&gbb1, g_gbb1);
    cudaGetSymbolAddress((void**)&gbb2, g_gbb2);

    // 0. conversions / packing / weight fusion
    wconv_kernel<<<(W_TOTAL + 384 + 255) / 256, 256>>>(q_w, k_w, v_w, d1_bias_w, d2_bias_w,
                                                       sc_w, bi1_w, bi2_w, q_b, k_b, v_b);
    fuse_gb_kernel<<<dim3(10, 8, 2), 256>>>(d1_embed_w, d1_scale_w, d1_bias_w,
                                            d1_embed_b, d1_scale_b, d1_bias_b,
                                            d2_embed_w, d2_scale_w, d2_bias_w,
                                            d2_embed_b, d2_scale_b, d2_bias_b,
                                            wh + WO_GB1, gbb1, wh + WO_GB2, gbb2);
    cvt_f2h_kernel<<<(int)(((long)NB * CHW / 8 + 255) / 256), 256>>>(x, xh, (long)NB * CHW);
    concat_aux_kernel<<<dim3(2, AUXK, NB), 256>>>(edge, seg, pe, ps);

    // 1. ADN-1 gamma/betaS directly from aux (fused weights, K=320)
    {
        GP p = {};
        p.A = wh + WO_GB1; p.lda = AUXK; p.sA = 0;
        p.B = auxh; p.ldb = HW; p.sB = (long)AUXK * HW;
        p.N = HW; p.sC = CHW; p.nkt = AUXK / 64; p.mode = EP_GB;
        p.bias = gbb1; p.ohh = gamh; p.ohh2 = beth;
        rung(false, false, 32, 2, NB, p);
    }

    // 2. q/k/v conv1x1 merged (M=384), fused LN stats
    cudaMemsetAsync(acc, 0, 96 * sizeof(float));
    {
        GP p = {};
        p.A = wh + WO_QKV; p.lda = 128; p.sA = 0;
        p.B = xh; p.ldb = HW; p.sB = CHW;
        p.N = HW; p.sC = 3L * CHW; p.nkt = 2; p.mode = EP_LIN; p.lng = 1;
        p.bias = qkvb; p.ohh = t0h; p.acc = acc;
        rung(false, false, 32, 3, NB, p);
    }
    ln_final_kernel<<<48, 32>>>();

    // 3. ADN-apply merged (48 z), fused patched writes
    {
        GP p = {};
        p.A = wh + WO_B1; p.lda = 256; p.sA = 0;
        p.B = t0h; p.ldb = HW; p.sB = CHW;
        p.N = HW; p.sC = CHW; p.nkt = 2; p.mode = EP_QKV3;
        p.t0h = t0h; p.gamh = gamh; p.beth = beth; p.stats = stats;
        p.d1q = qp1; p.d1k = kp1; p.d1v = vp1;
        p.d2q = qp2; p.d2k = kp2; p.d2v = vp2;
        rung(false, false, 32, 1, 48, p);
    }

    // 4. attention scores merged: score1 (y 0..7) + score2 (y == 8)
    {
        GP p = {};
        p.A = qp1; p.lda = 256; p.sA = 1024L * 256;
        p.B = kp1; p.ldb = 256; p.sB = 1024L * 256;
        p.N = 1024; p.sC = 1024L * 1024; p.nkt = 4; p.mode = EP_SCORE; p.scale = 0.0625f;
        p.ohh = s1h;
        p.A2g = qp2; p.lda2 = 1024; p.sA2 = 256L * 1024;
        p.B2g = kp2; p.ldb2 = 1024; p.sB2 = 256L * 1024;
        p.N2 = 256; p.nkt2 = 16; p.mT2 = 2; p.sC2 = 256L * 256;
        p.scale2 = 0.03125f; p.out2 = s2h;
        rung(true, false, 8, 9, NB, p);
    }
    softmax_both_kernel<<<NB * 1024 + NB * 256, 256>>>(s1h, s2h);

    // 5. PV1
    cudaMemsetAsync(acc, 0, 32 * sizeof(float));
    {
        GP p = {};
        p.A = s1h; p.lda = 1024; p.sA = 1024L * 1024;
        p.B = vp1; p.ldb = 256; p.sB = 1024L * 256;
        p.N = 256; p.sC = CHW; p.nkt = 16; p.mode = EP_PV1; p.lng = 2;
        p.xres = x; p.ohh = midh; p.acc = acc;
        rung(false, false, 2, 8, NB, p);
    }
    // 6. PV2
    {
        GP p = {};
        p.A = s2h; p.lda = 256; p.sA = 256L * 256;
        p.B = vp2; p.ldb = 1024; p.sB = 256L * 1024;
        p.N = 1024; p.sC = CHW; p.nkt = 4; p.mode = EP_PV2; p.lng = 2;
        p.xres = x; p.ohh = midh; p.acc = acc;
        rung(false, false, 8, 2, NB, p);
    }
    ln_final_kernel<<<16, 32>>>();

    // 7. ADN-2: gamma/betaS from aux (fused), then apply
    {
        GP p = {};
        p.A = wh + WO_GB2; p.lda = AUXK; p.sA = 0;
        p.B = auxh; p.ldb = HW; p.sB = (long)AUXK * HW;
        p.N = HW; p.sC = CHW; p.nkt = AUXK / 64; p.mode = EP_GB;
        p.bias = gbb2; p.ohh = gamh; p.ohh2 = beth;
        rung(false, false, 32, 2, NB, p);
    }
    {
        GP p = {};
        p.A = wh + WO_B2; p.lda = 256; p.sA = 0;
        p.B = midh; p.ldb = HW; p.sB = CHW;
        p.N = HW; p.sC = CHW; p.nkt = 2; p.mode = EP_ADN;
        p.t0h = midh; p.gamh = gamh; p.beth = beth; p.stats = stats;
        p.ohh = oh;
        rung(false, false, 32, 1, NB, p);
    }

    // 8. conv3x3 chain: sc+bi1 merged, then final
    {
        GP p = {};
        p.A = wh + WO_SC; p.lda = 1152; p.sA = 0;
        p.B = oh; p.ldb = 0; p.sB = CHW;
        p.N = HW; p.sC = CHW; p.nkt = 18;
        p.mode = EP_TANH; p.dil = 1; p.bias = sc_b; p.ohh = gfh;
        p.A2 = wh + WO_BI1; p.mode2c = EP_GELU; p.dil2 = 2; p.bias2c = bi1_b; p.ohh2 = tmph;
        rung(false, true, 32, 2, NB, p);
    }
    {
        GP p = {};
        p.A = wh + WO_BI2; p.lda = 1152; p.sA = 0;
        p.B = tmph; p.ldb = 0; p.sB = CHW;
        p.N = HW; p.sC = CHW; p.nkt = 18; p.mode = EP_FINAL; p.dil = 1;
        p.bias = bi2_b; p.midh = midh; p.gfh = gfh; p.of = out;
        rung(false, true, 32, 1, NB, p);
    }
}

// round 17
// speedup vs baseline: 1.1017x; 1.0122x over previous
#include <cuda_runtime.h>
#include <cuda_fp16.h>
#include <math.h>
#include <stdint.h>

// ---------------- problem constants ----------------
#define NB 16
#define HW 4096
#define CHW (128*HW)          // 524288
#define AUXC 277
#define AUXK 320

// ---------------- weight pack offsets (halfs) ----------------
#define WO_QKV  0             // [384][128]
#define WO_GB1  49152         // [256][320]  fused (S|Bh)·E
#define WO_B1   131072        // [128][256]
#define WO_GB2  163840        // [256][320]
#define WO_B2   245760        // [128][256]
#define WO_SC   278528        // [128][1152] plane-major
#define WO_BI1  425984
#define WO_BI2  573440
#define W_TOTAL 720896

// ---------------- scratch ----------------
__device__ __align__(256) half  g_wh  [W_TOTAL];
__device__ float g_qkvb[384];
__device__ float g_gbb1[256];
__device__ float g_gbb2[256];
__device__ __align__(256) half  g_auxh[(long)NB*AUXK*HW];
__device__ __align__(256) half  g_xh  [(long)NB*CHW];
__device__ __align__(256) half  g_t0h [(long)NB*3*CHW];
__device__ __align__(256) half  g_gamh[(long)NB*CHW];
__device__ __align__(256) half  g_beth[(long)NB*CHW];
__device__ __align__(256) half  g_midh[(long)NB*CHW];
__device__ __align__(256) half  g_oh  [(long)NB*CHW];
__device__ __align__(256) half  g_gfh [(long)NB*CHW];
__device__ __align__(256) half  g_tmph[(long)NB*CHW];
__device__ __align__(256) half  g_qp1 [NB*1024L*256];
__device__ __align__(256) half  g_kp1 [NB*1024L*256];
__device__ __align__(256) half  g_vp1 [NB*1024L*256];
__device__ __align__(256) half  g_qp2 [NB*256L*1024];
__device__ __align__(256) half  g_kp2 [NB*256L*1024];
__device__ __align__(256) half  g_vp2 [NB*256L*1024];
__device__ __align__(256) half  g_s1h [NB*1024L*1024];
__device__ __align__(256) half  g_s2h [NB*256L*256];
__device__ float g_stats[96];
__device__ float g_acc  [96];

// ---------------- epilogue modes ----------------
#define EP_LIN   0
#define EP_GB    1
#define EP_QKV3  2
#define EP_ADN   3
#define EP_SCORE 4
#define EP_PV1   5
#define EP_PV2   6
#define EP_TANH  7
#define EP_GELU  8
#define EP_FINAL 9

// ---------------- smem geometry (halfs), Kt = 64 ----------------
#define A_LDH 72
#define A_ROWB 144
#define BK_LDH 136
#define BK_ROWB 272
#define STAGE_HALFS 18432
#define STAGE_BYTES 36864
#define B_OFF_H 9216
#define GSM_BYTES (3*STAGE_BYTES)   // 110592 (3 stages; conv uses 2)

// ---------------- asm helpers ----------------
__device__ __forceinline__ uint32_t smem_u32(const void* p) {
    uint32_t a;
    asm("{ .reg .u64 t; cvta.to.shared.u64 t, %1; cvt.u32.u64 %0, t; }" : "=r"(a) : "l"(p));
    return a;
}
__device__ __forceinline__ void cp16(uint32_t dst, const void* src) {
    asm volatile("cp.async.cg.shared.global [%0], [%1], 16;" :: "r"(dst), "l"(src));
}
#define CP_COMMIT() asm volatile("cp.async.commit_group;")
#define CP_WAIT1()  asm volatile("cp.async.wait_group 1;")
#define CP_WAIT0()  asm volatile("cp.async.wait_group 0;")
__device__ __forceinline__ void ldsm_x4(uint32_t* r, uint32_t addr) {
    asm volatile("ldmatrix.sync.aligned.m8n8.x4.shared.b16 {%0,%1,%2,%3}, [%4];"
                 : "=r"(r[0]), "=r"(r[1]), "=r"(r[2]), "=r"(r[3]) : "r"(addr));
}
__device__ __forceinline__ void ldsm_x4t(uint32_t* r, uint32_t addr) {
    asm volatile("ldmatrix.sync.aligned.m8n8.x4.trans.shared.b16 {%0,%1,%2,%3}, [%4];"
                 : "=r"(r[0]), "=r"(r[1]), "=r"(r[2]), "=r"(r[3]) : "r"(addr));
}
__device__ __forceinline__ void mma_f16(float* c,
                                        uint32_t a0, uint32_t a1, uint32_t a2, uint32_t a3,
                                        uint32_t b0, uint32_t b1) {
    asm volatile(
        "mma.sync.aligned.m16n8k16.row.col.f32.f16.f16.f32 "
        "{%0,%1,%2,%3}, {%4,%5,%6,%7}, {%8,%9}, {%0,%1,%2,%3};"
        : "+f"(c[0]), "+f"(c[1]), "+f"(c[2]), "+f"(c[3])
        : "r"(a0), "r"(a1), "r"(a2), "r"(a3), "r"(b0), "r"(b1));
}

// ---------------- GEMM params ----------------
struct GP {
    const half* A; int lda; long sA;
    const half* B; int ldb; long sB;
    int N; long sC; int nkt;
    int mode; float scale; int dil; int lng;
    const float* bias;
    const half* t0h; const half* gamh; const half* beth; const float* stats;
    const float* xres; const half* midh; const half* gfh;
    float* of; half* ohh; half* ohh2;
    half* d1q; half* d1k; half* d1v;
    half* d2q; half* d2k; half* d2v;
    float* acc;
    // conv merged variant (blockIdx.y == 1)
    const half* A2; const float* bias2c; int dil2; int mode2c;
    // secondary GEMM (merged TRANSB score launch)
    const half* A2g; long sA2;
    const half* B2g; int ldb2; long sB2;
    int N2, nkt2, mT2, lda2;
    long sC2; float scale2; half* out2;
};

// ================= fp16 tensor-core GEMM, Kt=64 =================
template<bool TRANSB, bool CONV>
__global__ void __launch_bounds__(256)
hgemm17(GP g) {
    extern __shared__ __align__(16) half sm[];
    int bb = blockIdx.z;
    int n0 = blockIdx.x * 128;
    int m0 = CONV ? 0 : blockIdx.y * 128;

    const half* Aw = g.A;
    const half* Bw = g.B;
    int lda = g.lda, ldb = g.ldb;
    long sA = g.sA, sB = g.sB, sC = g.sC;
    int NN = g.N, nkt = g.nkt;
    int dil = g.dil;
    int mode = g.mode;
    float scale = g.scale;
    const float* biasL = g.bias;
    half* ohhL = g.ohh;

    if (CONV && blockIdx.y == 1) {
        Aw = g.A2; dil = g.dil2; mode = g.mode2c; biasL = g.bias2c; ohhL = g.ohh2;
    }
    if (TRANSB && g.N2 && blockIdx.y == gridDim.y - 1) {
        int t2x = g.N2 >> 7;
        int id = blockIdx.x;
        if (id >= g.mT2 * t2x) return;
        m0 = (id / t2x) * 128;
        n0 = (id % t2x) * 128;
        Aw = g.A2g; Bw = g.B2g;
        lda = g.lda2; ldb = g.ldb2;
        sA = g.sA2; sB = g.sB2; sC = g.sC2;
        NN = g.N2; nkt = g.nkt2; scale = g.scale2;
        ohhL = g.out2;
    }
    const half* Ap = Aw + (long)bb * sA;
    const half* Bp = Bw + (long)bb * sB;

    int tid  = threadIdx.x;
    int lane = tid & 31;
    int warp = tid >> 5;
    int wm = (warp >> 2) * 64;
    int wn = (warp & 3) * 32;

    int arow  = tid >> 1;
    int akseg = (tid & 1) * 32;
    int bkr = tid >> 2;
    int bns = (tid & 3) * 32;
    int cn    = tid & 127;
    int ckseg = (tid >> 7) * 32;

    uint32_t sbase = smem_u32(sm);
    int rowsel = lane & 15;
    int colsel = (lane >> 4) * 16;

    float acc[4][4][4] = {};

    auto do_compute = [&](uint32_t stA) {
        uint32_t stB = stA + B_OFF_H * 2;
        uint32_t abase = stA + (uint32_t)(wm + rowsel) * A_ROWB + colsel;
#pragma unroll
        for (int ks = 0; ks < 4; ks++) {
            uint32_t af[4][4];
#pragma unroll
            for (int mt = 0; mt < 4; mt++)
                ldsm_x4(af[mt], abase + mt * 16 * A_ROWB + ks * 32);
            uint32_t bf[2][4];
            if (TRANSB || CONV) {
                uint32_t bbase = stB + (uint32_t)(wn + rowsel) * A_ROWB + colsel;
#pragma unroll
                for (int ntp = 0; ntp < 2; ntp++)
                    ldsm_x4(bf[ntp], bbase + ntp * 16 * A_ROWB + ks * 32);
            } else {
                uint32_t bbase = stB + (uint32_t)(ks * 16 + rowsel) * BK_ROWB
                               + (uint32_t)(wn + (lane >> 4) * 8) * 2;
#pragma unroll
                for (int ntp = 0; ntp < 2; ntp++)
                    ldsm_x4t(bf[ntp], bbase + ntp * 32);
            }
#pragma unroll
            for (int mt = 0; mt < 4; mt++) {
#pragma unroll
                for (int nt = 0; nt < 4; nt++) {
                    int ntp = nt >> 1, par = nt & 1;
                    uint32_t b0, b1;
                    if (TRANSB || CONV) { b0 = bf[ntp][par];     b1 = bf[ntp][par + 2]; }
                    else                { b0 = bf[ntp][par * 2]; b1 = bf[ntp][par * 2 + 1]; }
                    mma_f16(acc[mt][nt],
                            af[mt][0], af[mt][1], af[mt][2], af[mt][3], b0, b1);
                }
            }
        }
    };

    if (!CONV) {
        // ---- 3-stage cp.async pipeline (2-tile lookahead) ----
        auto load_async = [&](int t) {
            uint32_t st = sbase + (uint32_t)((t % 3) * STAGE_BYTES);
            int kt = t * 64;
            const half* ar = Ap + (long)(m0 + arow) * lda + kt + akseg;
            uint32_t da = st + (uint32_t)arow * A_ROWB + akseg * 2;
#pragma unroll
            for (int j = 0; j < 4; j++) cp16(da + j * 16, ar + j * 8);
            if (TRANSB) {
                const half* br = Bp + (long)(n0 + arow) * ldb + kt + akseg;
                uint32_t db = st + B_OFF_H * 2 + (uint32_t)arow * A_ROWB + akseg * 2;
#pragma unroll
                for (int j = 0; j < 4; j++) cp16(db + j * 16, br + j * 8);
            } else {
                const half* br = Bp + (long)(kt + bkr) * ldb + n0 + bns;
                uint32_t db = st + B_OFF_H * 2 + (uint32_t)bkr * BK_ROWB + bns * 2;
#pragma unroll
                for (int j = 0; j < 4; j++) cp16(db + j * 16, br + j * 8);
            }
        };
        if (nkt > 0) { load_async(0); CP_COMMIT(); }
        if (nkt > 1) { load_async(1); CP_COMMIT(); }
        for (int it = 0; it < nkt; it++) {
            if (it + 1 < nkt) CP_WAIT1(); else CP_WAIT0();
            __syncthreads();
            if (it + 2 < nkt) { load_async(it + 2); CP_COMMIT(); }
            do_compute(sbase + (uint32_t)((it % 3) * STAGE_BYTES));
        }
        __syncthreads();
    } else {
        // ---- conv: 2-stage register-staged loop (unchanged) ----
        uint4 ra[4], rb[4];
        for (int it = 0; it <= nkt; it++) {
            if (it < nkt) {
                int kt = it * 64;
                const half* ar = Ap + (long)(m0 + arow) * lda + kt + akseg;
#pragma unroll
                for (int j = 0; j < 4; j++) ra[j] = *(const uint4*)(ar + j * 8);
                int tap = kt >> 7;
                int cb  = (kt & 127) + ckseg;
                int dy = (tap / 3 - 1) * dil;
                int dx = (tap % 3 - 1) * dil;
                int p = n0 + cn;
                int h = (p >> 6) + dy;
                int w = (p & 63) + dx;
                half rc[32];
                if ((unsigned)h < 64u && (unsigned)w < 64u) {
                    const half* base = Bp + (long)cb * HW + h * 64 + w;
#pragma unroll
                    for (int j = 0; j < 32; j++) rc[j] = base[(long)j * HW];
                } else {
#pragma unroll
                    for (int j = 0; j < 32; j++) rc[j] = __ushort_as_half((unsigned short)0);
                }
#pragma unroll
                for (int j = 0; j < 4; j++) rb[j] = ((uint4*)rc)[j];
            }
            if (it > 0)
                do_compute(sbase + (uint32_t)(((it - 1) & 1) * STAGE_BYTES));
            if (it < nkt) {
                half* stA = sm + (it & 1) * STAGE_HALFS;
                half* da = stA + arow * A_LDH + akseg;
#pragma unroll
                for (int j = 0; j < 4; j++) *(uint4*)(da + j * 8) = ra[j];
                half* db = stA + B_OFF_H + cn * A_LDH + ckseg;
#pragma unroll
                for (int j = 0; j < 4; j++) *(uint4*)(db + j * 8) = rb[j];
            }
            __syncthreads();
        }
    }

    // ---- epilogue (pair-vectorized) ----
    int r  = lane >> 2;
    int cg = lane & 3;
    long bbC = (long)bb * sC;
    float mu = 0.f, rs = 0.f;
    if (mode == EP_QKV3 || mode == EP_ADN) { mu = g.stats[2 * bb]; rs = g.stats[2 * bb + 1]; }
    int b3 = bb / 3, t3 = bb - 3 * (bb / 3);
    float lsum = 0.f, lsq = 0.f;

    auto emit2 = [&](float v0, float v1, int m, int n) {
        long li = (long)m * NN + n;
        if (mode == EP_LIN) {
            float r0 = v0 + biasL[m], r1 = v1 + biasL[m];
            if (g.lng) { lsum += r0 + r1; lsq += r0 * r0 + r1 * r1; }
            *(half2*)(ohhL + bbC + li) = __floats2half2_rn(r0, r1);
        } else if (mode == EP_GB) {
            float r0 = v0 + biasL[m], r1 = v1 + biasL[m];
            long o = (long)bb * CHW + (long)(m & 127) * HW + n;
            half2 hv = __floats2half2_rn(r0, r1);
            if (m < 128) *(half2*)(ohhL + o) = hv;
            else         *(half2*)(g.ohh2 + o) = hv;
        } else if (mode == EP_QKV3) {
            long ti = bbC + li;
            long gi = (long)b3 * CHW + li;
            half2 tp = *(const half2*)(g.t0h + ti);
            half2 gp = *(const half2*)(g.gamh + gi);
            half2 bp = *(const half2*)(g.beth + gi);
            float val0 = (__low2float(tp)  - mu) * rs * __low2float(gp)  + v0 + __low2float(bp);
            float val1 = (__high2float(tp) - mu) * rs * __high2float(gp) + v1 + __high2float(bp);
            half2 hv = __floats2half2_rn(val0, val1);
            int h = n >> 6, w = n & 63;
            if (m < 64) {
                int tk = (h >> 1) * 32 + (w >> 1);
                int d  = m * 4 + (h & 1) * 2;
                half* dst = (t3 == 0) ? g.d1q : (t3 == 1) ? g.d1k : g.d1v;
                *(half2*)(dst + (long)b3 * (1024L * 256) + (long)tk * 256 + d) = hv;
            } else {
                int tk = (h >> 2) * 16 + (w >> 2);
                int d  = (m - 64) * 16 + (h & 3) * 4 + (w & 3);
                half* dst = (t3 == 0) ? g.d2q : (t3 == 1) ? g.d2k : g.d2v;
                *(half2*)(dst + (long)b3 * (256L * 1024) + (long)tk * 1024 + d) = hv;
            }
        } else if (mode == EP_ADN) {
            long gi = bbC + li;
            half2 tp = *(const half2*)(g.t0h + gi);
            half2 gp = *(const half2*)(g.gamh + gi);
            half2 bp = *(const half2*)(g.beth + gi);
            float r0 = (__low2float(tp)  - mu) * rs * __low2float(gp)  + v0 + __low2float(bp);
            float r1 = (__high2float(tp) - mu) * rs * __high2float(gp) + v1 + __high2float(bp);
            *(half2*)(ohhL + gi) = __floats2half2_rn(r0, r1);
        } else if (mode == EP_SCORE) {
            *(half2*)(ohhL + bbC + li) = __floats2half2_rn(v0 * scale, v1 * scale);
        } else if (mode == EP_PV1) {
            int c  = n >> 2;
            int py = (n >> 1) & 1;
            int h = (m >> 5) * 2 + py, w = (m & 31) * 2;
            long tgt = bbC + (long)c * HW + h * 64 + w;
            float2 xr = *(const float2*)(g.xres + tgt);
            float r0 = xr.x + v0, r1 = xr.y + v1;
            lsum += r0 + r1; lsq += r0 * r0 + r1 * r1;
            *(half2*)(ohhL + tgt) = __floats2half2_rn(r0, r1);
        } else if (mode == EP_PV2) {
            int c  = 64 + (n >> 4);
            int py = (n >> 2) & 3, px = n & 3;
            int h = (m >> 4) * 4 + py, w = (m & 15) * 4 + px;
            long tgt = bbC + (long)c * HW + h * 64 + w;
            float2 xr = *(const float2*)(g.xres + tgt);
            float r0 = xr.x + v0, r1 = xr.y + v1;
            lsum += r0 + r1; lsq += r0 * r0 + r1 * r1;
            *(half2*)(ohhL + tgt) = __floats2half2_rn(r0, r1);
        } else if (mode == EP_TANH) {
            *(half2*)(ohhL + bbC + li) =
                __floats2half2_rn(tanhf(v0 + biasL[m]), tanhf(v1 + biasL[m]));
        } else if (mode == EP_GELU) {
            float u0 = v0 + biasL[m], u1 = v1 + biasL[m];
            float r0 = 0.5f * u0 * (1.f + erff(u0 * 0.70710678118654752f));
            float r1 = 0.5f * u1 * (1.f + erff(u1 * 0.70710678118654752f));
            *(half2*)(ohhL + bbC + li) = __floats2half2_rn(r0, r1);
        } else { // EP_FINAL
            long gi = bbC + li;
            half2 mh = *(const half2*)(g.midh + gi);
            half2 gh = *(const half2*)(g.gfh + gi);
            float2 o;
            o.x = __low2float(mh)  * __low2float(gh)  + v0 + biasL[m];
            o.y = __high2float(mh) * __high2float(gh) + v1 + biasL[m];
            *(float2*)(g.of + gi) = o;
        }
    };

#pragma unroll
    for (int mt = 0; mt < 4; mt++) {
#pragma unroll
        for (int nt = 0; nt < 4; nt++) {
            int m1 = m0 + wm + mt * 16 + r;
            int nn = n0 + wn + nt * 8 + cg * 2;
            emit2(acc[mt][nt][0], acc[mt][nt][1], m1, nn);
            emit2(acc[mt][nt][2], acc[mt][nt][3], m1 + 8, nn);
        }
    }

    // ---- fused LN partial-stats reduction ----
    if (g.lng) {
#pragma unroll
        for (int o = 16; o; o >>= 1) {
            lsum += __shfl_xor_sync(0xffffffffu, lsum, o);
            lsq  += __shfl_xor_sync(0xffffffffu, lsq,  o);
        }
        float* smf = (float*)sm;
        if (lane == 0) { smf[warp * 2] = lsum; smf[warp * 2 + 1] = lsq; }
        __syncthreads();
        if (warp == 0 && lane < 8) {
            lsum = smf[lane * 2]; lsq = smf[lane * 2 + 1];
#pragma unroll
            for (int o = 4; o; o >>= 1) {
                lsum += __shfl_xor_sync(0xffu, lsum, o);
                lsq  += __shfl_xor_sync(0xffu, lsq,  o);
            }
            if (lane == 0) {
                int grp = (g.lng == 1) ? bb * 3 + (m0 >> 7) : bb;
                atomicAdd(&g.acc[2 * grp],     lsum);
                atomicAdd(&g.acc[2 * grp + 1], lsq);
            }
        }
    }
}

// ================= weight repack + bias pack =================
__global__ void __launch_bounds__(256)
wconv_kernel(const float* qw, const float* kw, const float* vw,
             const float* b1, const float* b2,
             const float* sc, const float* bi1, const float* bi2,
             const float* qb, const float* kb, const float* vb) {
    int i = blockIdx.x * 256 + threadIdx.x;
    if (i >= W_TOTAL) {
        int j = i - W_TOTAL;
        if (j < 384) g_qkvb[j] = j < 128 ? qb[j] : j < 256 ? kb[j - 128] : vb[j - 256];
        return;
    }
    float v;
    if (i < WO_GB1) {
        int t = i >> 14, j = i & 16383;
        v = (t == 0 ? qw : t == 1 ? kw : vw)[j];
    } else if (i < WO_B1) {
        return;
    } else if (i < WO_GB2) {
        v = b1[i - WO_B1];
    } else if (i < WO_B2) {
        return;
    } else if (i < WO_SC) {
        v = b2[i - WO_B2];
    } else {
        int j = i - WO_SC;
        int blk = j / 147456, t = j % 147456;
        int o = t / 1152, rr = t % 1152;
        int tap = rr >> 7, c = rr & 127;
        const float* w = (blk == 0 ? sc : blk == 1 ? bi1 : bi2);
        v = w[((o * 128 + c) * 3 + tap / 3) * 3 + (tap % 3)];
    }
    g_wh[i] = __float2half_rn(v);
}

// ================= tiled fuse, both ADN sets in one launch =================
__global__ void __launch_bounds__(256)
fuse_gb_kernel(const float* e1,  const float* sw1, const float* bw1,
               const float* eb1, const float* sb1, const float* bb1,
               const float* e2,  const float* sw2, const float* bw2,
               const float* eb2, const float* sb2, const float* bb2,
               half* dstW1, float* dstB1, half* dstW2, float* dstB2) {
    const float *e, *sw, *bw, *eb, *sb, *bbv;
    half* dstW; float* dstB;
    if (blockIdx.z == 0) { e = e1; sw = sw1; bw = bw1; eb = eb1; sb = sb1; bbv = bb1; dstW = dstW1; dstB = dstB1; }
    else                 { e = e2; sw = sw2; bw = bw2; eb = eb2; sb = sb2; bbv = bb2; dstW = dstW2; dstB = dstB2; }

    __shared__ float w2s[32 * 132];
    __shared__ float es [128 * 33];
    int r0 = blockIdx.y * 32;
    int c0 = blockIdx.x * 32;
    int tid = threadIdx.x;

#pragma unroll
    for (int i = 0; i < 16; i++) {
        int idx = tid + i * 256;
        int rr = idx >> 7, k = idx & 127;
        int r = r0 + rr;
        float v = (r < 128) ? sw[r * 128 + k] : bw[(r - 128) * 256 + 128 + k];
        w2s[rr * 132 + k] = v;
    }
#pragma unroll
    for (int i = 0; i < 16; i++) {
        int idx = tid + i * 256;
        int k = idx >> 5, cc = idx & 31;
        int c = c0 + cc;
        float v = 0.f;
        if (c < AUXC)      v = e[k * AUXC + c];
        else if (c == 319) v = eb[k];
        es[k * 33 + cc] = v;
    }
    __syncthreads();

    int tr = (tid >> 4) * 2;
    int tc = (tid & 15) * 2;
    float a00 = 0.f, a01 = 0.f, a10 = 0.f, a11 = 0.f;
#pragma unroll 8
    for (int k = 0; k < 128; k++) {
        float b0 = es[k * 33 + tc];
        float b1 = es[k * 33 + tc + 1];
        float w0 = w2s[tr * 132 + k];
        float w1 = w2s[(tr + 1) * 132 + k];
        a00 = fmaf(w0, b0, a00); a01 = fmaf(w0, b1, a01);
        a10 = fmaf(w1, b0, a10); a11 = fmaf(w1, b1, a11);
    }

    float vv[2][2] = {{a00, a01}, {a10, a11}};
#pragma unroll
    for (int i = 0; i < 2; i++) {
        int r = r0 + tr + i;
#pragma unroll
        for (int j = 0; j < 2; j++) {
            int c = c0 + tc + j;
            float v = vv[i][j];
            if (c == 319) {
                dstB[r] = v + ((r < 128) ? sb[r] : bbv[r - 128]);
                dstW[(long)r * 320 + c] = __float2half_rn(0.f);
            } else {
                dstW[(long)r * 320 + c] = __float2half_rn(v);
            }
        }
    }
}

// ================= concat aux =================
__global__ void __launch_bounds__(256)
concat_aux_kernel(const float* __restrict__ edge, const float* __restrict__ seg,
                  const float* __restrict__ pe,   const float* __restrict__ ps) {
    int b = blockIdx.z;
    int c = blockIdx.y;
    int p0 = blockIdx.x * 2048 + threadIdx.x * 8;
    half* dst = g_auxh + ((long)b * AUXK + c) * HW + p0;
    half h[8];
    if (c < AUXC) {
        const float* src;
        if (c < 128)       src = edge + ((long)b * 128 + c) * HW;
        else if (c < 256)  src = seg  + ((long)b * 128 + (c - 128)) * HW;
        else if (c == 256) src = pe   + (long)b * HW;
        else               src = ps   + ((long)b * 20 + (c - 257)) * HW;
        float4 v0 = *(const float4*)(src + p0);
        float4 v1 = *(const float4*)(src + p0 + 4);
        h[0] = __float2half_rn(v0.x); h[1] = __float2half_rn(v0.y);
        h[2] = __float2half_rn(v0.z); h[3] = __float2half_rn(v0.w);
        h[4] = __float2half_rn(v1.x); h[5] = __float2half_rn(v1.y);
        h[6] = __float2half_rn(v1.z); h[7] = __float2half_rn(v1.w);
    } else {
#pragma unroll
        for (int j = 0; j < 8; j++) h[j] = __ushort_as_half((unsigned short)0);
    }
    *(uint4*)dst = *(uint4*)h;
}

__global__ void __launch_bounds__(256)
cvt_f2h_kernel(const float* __restrict__ src, half* __restrict__ dst, long n) {
    long i = ((long)blockIdx.x * 256 + threadIdx.x) * 8;
    if (i >= n) return;
    float4 v0 = *(const float4*)(src + i);
    float4 v1 = *(const float4*)(src + i + 4);
    half h[8];
    h[0] = __float2half_rn(v0.x); h[1] = __float2half_rn(v0.y);
    h[2] = __float2half_rn(v0.z); h[3] = __float2half_rn(v0.w);
    h[4] = __float2half_rn(v1.x); h[5] = __float2half_rn(v1.y);
    h[6] = __float2half_rn(v1.z); h[7] = __float2half_rn(v1.w);
    *(uint4*)(dst + i) = *(uint4*)h;
}

// ================= LN finalize =================
__global__ void ln_final_kernel() {
    int b = blockIdx.x;
    if (threadIdx.x == 0) {
        float s = g_acc[2 * b], q = g_acc[2 * b + 1];
        float mu = s / (float)CHW;
        float var = q / (float)CHW - mu * mu;
        g_stats[2 * b]     = mu;
        g_stats[2 * b + 1] = rsqrtf(var + 1e-5f);
    }
}

// ================= merged softmax for s1 + s2 =================
__global__ void __launch_bounds__(256)
softmax_both_kernel(half* __restrict__ S1, half* __restrict__ S2) {
    long bid = blockIdx.x;
    half* p;
    int VPT;
    if (bid < (long)NB * 1024) {
        p = S1 + bid * 1024;
        VPT = 4;
    } else {
        p = S2 + (bid - (long)NB * 1024) * 256;
        VPT = 1;
    }
    half* o = p;
    int tid = threadIdx.x;
    __shared__ float sh[8];
    float v[4];
    if (VPT == 4) {
        uint2 d = ((const uint2*)p)[tid];
        half2 h0 = *(half2*)&d.x, h1 = *(half2*)&d.y;
        v[0] = __low2float(h0); v[1] = __high2float(h0);
        v[2] = __low2float(h1); v[3] = __high2float(h1);
    } else {
        v[0] = __half2float(p[tid]);
    }

    float mx = -3.4e38f;
    for (int i = 0; i < VPT; i++) mx = fmaxf(mx, v[i]);
#pragma unroll
    for (int og = 16; og; og >>= 1) mx = fmaxf(mx, __shfl_xor_sync(0xffffffffu, mx, og));
    if ((tid & 31) == 0) sh[tid >> 5] = mx;
    __syncthreads();
    if (tid < 8) {
        float t = sh[tid];
#pragma unroll
        for (int og = 4; og; og >>= 1) t = fmaxf(t, __shfl_xor_sync(0xffu, t, og));
        if (tid == 0) sh[0] = t;
    }
    __syncthreads();
    mx = sh[0];
    __syncthreads();

    float s = 0.f;
    for (int i = 0; i < VPT; i++) { v[i] = __expf(v[i] - mx); s += v[i]; }
#pragma unroll
    for (int og = 16; og; og >>= 1) s += __shfl_xor_sync(0xffffffffu, s, og);
    if ((tid & 31) == 0) sh[tid >> 5] = s;
    __syncthreads();
    if (tid < 8) {
        float t = sh[tid];
#pragma unroll
        for (int og = 4; og; og >>= 1) t += __shfl_xor_sync(0xffu, t, og);
        if (tid == 0) sh[0] = t;
    }
    __syncthreads();
    float inv = 1.f / sh[0];
    if (VPT == 4) {
        half2 h0 = __floats2half2_rn(v[0] * inv, v[1] * inv);
        half2 h1 = __floats2half2_rn(v[2] * inv, v[3] * inv);
        uint2 d; d.x = *(uint32_t*)&h0; d.y = *(uint32_t*)&h1;
        ((uint2*)o)[tid] = d;
    } else {
        o[tid] = __float2half_rn(v[0] * inv);
    }
}

// ================= host =================
static void rung(bool transb, bool conv, int nT, int mT, int zT, const GP& g) {
    dim3 grid(nT, mT, zT);
    if (conv)        hgemm17<false, true ><<<grid, 256, GSM_BYTES>>>(g);
    else if (transb) hgemm17<true,  false><<<grid, 256, GSM_BYTES>>>(g);
    else             hgemm17<false, false><<<grid, 256, GSM_BYTES>>>(g);
}

extern "C" void kernel_launch(void* const* d_in, const int* in_sizes, int n_in,
                              void* d_out, int out_size) {
    const float* x    = (const float*)d_in[0];
    const float* edge = (const float*)d_in[1];
    const float* seg  = (const float*)d_in[2];
    const float* pe   = (const float*)d_in[3];
    const float* ps   = (const float*)d_in[4];
    const float* q_w  = (const float*)d_in[5];
    const float* q_b  = (const float*)d_in[6];
    const float* k_w  = (const float*)d_in[7];
    const float* k_b  = (const float*)d_in[8];
    const float* v_w  = (const float*)d_in[9];
    const float* v_b  = (const float*)d_in[10];
    const float* d1_embed_w = (const float*)d_in[11];
    const float* d1_embed_b = (const float*)d_in[12];
    const float* d1_scale_w = (const float*)d_in[13];
    const float* d1_scale_b = (const float*)d_in[14];
    const float* d1_bias_w  = (const float*)d_in[15];
    const float* d1_bias_b  = (const float*)d_in[16];
    const float* d2_embed_w = (const float*)d_in[17];
    const float* d2_embed_b = (const float*)d_in[18];
    const float* d2_scale_w = (const float*)d_in[19];
    const float* d2_scale_b = (const float*)d_in[20];
    const float* d2_bias_w  = (const float*)d_in[21];
    const float* d2_bias_b  = (const float*)d_in[22];
    const float* sc_w  = (const float*)d_in[23];
    const float* sc_b  = (const float*)d_in[24];
    const float* bi1_w = (const float*)d_in[25];
    const float* bi1_b = (const float*)d_in[26];
    const float* bi2_w = (const float*)d_in[27];
    const float* bi2_b = (const float*)d_in[28];
    float* out = (float*)d_out;

    cudaFuncSetAttribute(hgemm17<false, false>, cudaFuncAttributeMaxDynamicSharedMemorySize, GSM_BYTES);
    cudaFuncSetAttribute(hgemm17<true,  false>, cudaFuncAttributeMaxDynamicSharedMemorySize, GSM_BYTES);
    cudaFuncSetAttribute(hgemm17<false, true >, cudaFuncAttributeMaxDynamicSharedMemorySize, GSM_BYTES);

    half *wh, *auxh, *xh, *t0h, *gamh, *beth, *midh, *oh, *gfh, *tmph;
    half *qp1, *kp1, *vp1, *qp2, *kp2, *vp2, *s1h, *s2h;
    float *stats, *acc, *qkvb, *gbb1, *gbb2;
    cudaGetSymbolAddress((void**)&wh,   g_wh);
    cudaGetSymbolAddress((void**)&auxh, g_auxh);
    cudaGetSymbolAddress((void**)&xh,   g_xh);
    cudaGetSymbolAddress((void**)&t0h,  g_t0h);
    cudaGetSymbolAddress((void**)&gamh, g_gamh);
    cudaGetSymbolAddress((void**)&beth, g_beth);
    cudaGetSymbolAddress((void**)&midh, g_midh);
    cudaGetSymbolAddress((void**)&oh,   g_oh);
    cudaGetSymbolAddress((void**)&gfh,  g_gfh);
    cudaGetSymbolAddress((void**)&tmph, g_tmph);
    cudaGetSymbolAddress((void**)&qp1,  g_qp1);
    cudaGetSymbolAddress((void**)&kp1,  g_kp1);
    cudaGetSymbolAddress((void**)&vp1,  g_vp1);
    cudaGetSymbolAddress((void**)&qp2,  g_qp2);
    cudaGetSymbolAddress((void**)&kp2,  g_kp2);
    cudaGetSymbolAddress((void**)&vp2,  g_vp2);
    cudaGetSymbolAddress((void**)&s1h,  g_s1h);
    cudaGetSymbolAddress((void**)&s2h,  g_s2h);
    cudaGetSymbolAddress((void**)&stats, g_stats);
    cudaGetSymbolAddress((void**)&acc,   g_acc);
    cudaGetSymbolAddress((void**)&qkvb, g_qkvb);
    cudaGetSymbolAddress((void**)&gbb1, g_gbb1);
    cudaGetSymbolAddress((void**)&gbb2, g_gbb2);

    // 0. conversions / packing / weight fusion
    wconv_kernel<<<(W_TOTAL + 384 + 255) / 256, 256>>>(q_w, k_w, v_w, d1_bias_w, d2_bias_w,
                                                       sc_w, bi1_w, bi2_w, q_b, k_b, v_b);
    fuse_gb_kernel<<<dim3(10, 8, 2), 256>>>(d1_embed_w, d1_scale_w, d1_bias_w,
                                            d1_embed_b, d1_scale_b, d1_bias_b,
                                            d2_embed_w, d2_scale_w, d2_bias_w,
                                            d2_embed_b, d2_scale_b, d2_bias_b,
                                            wh + WO_GB1, gbb1, wh + WO_GB2, gbb2);
    cvt_f2h_kernel<<<(int)(((long)NB * CHW / 8 + 255) / 256), 256>>>(x, xh, (long)NB * CHW);
    concat_aux_kernel<<<dim3(2, AUXK, NB), 256>>>(edge, seg, pe, ps);

    // 1. ADN-1 gamma/betaS directly from aux (fused weights, K=320)
    {
        GP p = {};
        p.A = wh + WO_GB1; p.lda = AUXK; p.sA = 0;
        p.B = auxh; p.ldb = HW; p.sB = (long)AUXK * HW;
        p.N = HW; p.sC = CHW; p.nkt = AUXK / 64; p.mode = EP_GB;
        p.bias = gbb1; p.ohh = gamh; p.ohh2 = beth;
        rung(false, false, 32, 2, NB, p);
    }

    // 2. q/k/v conv1x1 merged (M=384), fused LN stats
    cudaMemsetAsync(acc, 0, 96 * sizeof(float));
    {
        GP p = {};
        p.A = wh + WO_QKV; p.lda = 128; p.sA = 0;
        p.B = xh; p.ldb = HW; p.sB = CHW;
        p.N = HW; p.sC = 3L * CHW; p.nkt = 2; p.mode = EP_LIN; p.lng = 1;
        p.bias = qkvb; p.ohh = t0h; p.acc = acc;
        rung(false, false, 32, 3, NB, p);
    }
    ln_final_kernel<<<48, 32>>>();

    // 3. ADN-apply merged (48 z), fused patched writes
    {
        GP p = {};
        p.A = wh + WO_B1; p.lda = 256; p.sA = 0;
        p.B = t0h; p.ldb = HW; p.sB = CHW;
        p.N = HW; p.sC = CHW; p.nkt = 2; p.mode = EP_QKV3;
        p.t0h = t0h; p.gamh = gamh; p.beth = beth; p.stats = stats;
        p.d1q = qp1; p.d1k = kp1; p.d1v = vp1;
        p.d2q = qp2; p.d2k = kp2; p.d2v = vp2;
        rung(false, false, 32, 1, 48, p);
    }

    // 4. attention scores merged: score1 (y 0..7) + score2 (y == 8)
    {
        GP p = {};
        p.A = qp1; p.lda = 256; p.sA = 1024L * 256;
        p.B = kp1; p.ldb = 256; p.sB = 1024L * 256;
        p.N = 1024; p.sC = 1024L * 1024; p.nkt = 4; p.mode = EP_SCORE; p.scale = 0.0625f;
        p.ohh = s1h;
        p.A2g = qp2; p.lda2 = 1024; p.sA2 = 256L * 1024;
        p.B2g = kp2; p.ldb2 = 1024; p.sB2 = 256L * 1024;
        p.N2 = 256; p.nkt2 = 16; p.mT2 = 2; p.sC2 = 256L * 256;
        p.scale2 = 0.03125f; p.out2 = s2h;
        rung(true, false, 8, 9, NB, p);
    }
    softmax_both_kernel<<<NB * 1024 + NB * 256, 256>>>(s1h, s2h);

    // 5. PV1
    cudaMemsetAsync(acc, 0, 32 * sizeof(float));
    {
        GP p = {};
        p.A = s1h; p.lda = 1024; p.sA = 1024L * 1024;
        p.B = vp1; p.ldb = 256; p.sB = 1024L * 256;
        p.N = 256; p.sC = CHW; p.nkt = 16; p.mode = EP_PV1; p.lng = 2;
        p.xres = x; p.ohh = midh; p.acc = acc;
        rung(false, false, 2, 8, NB, p);
    }
    // 6. PV2
    {
        GP p = {};
        p.A = s2h; p.lda = 256; p.sA = 256L * 256;
        p.B = vp2; p.ldb = 1024; p.sB = 256L * 1024;
        p.N = 1024; p.sC = CHW; p.nkt = 4; p.mode = EP_PV2; p.lng = 2;
        p.xres = x; p.ohh = midh; p.acc = acc;
        rung(false, false, 8, 2, NB, p);
    }
    ln_final_kernel<<<16, 32>>>();

    // 7. ADN-2: gamma/betaS from aux (fused), then apply
    {
        GP p = {};
        p.A = wh + WO_GB2; p.lda = AUXK; p.sA = 0;
        p.B = auxh; p.ldb = HW; p.sB = (long)AUXK * HW;
        p.N = HW; p.sC = CHW; p.nkt = AUXK / 64; p.mode = EP_GB;
        p.bias = gbb2; p.ohh = gamh; p.ohh2 = beth;
        rung(false, false, 32, 2, NB, p);
    }
    {
        GP p = {};
        p.A = wh + WO_B2; p.lda = 256; p.sA = 0;
        p.B = midh; p.ldb = HW; p.sB = CHW;
        p.N = HW; p.sC = CHW; p.nkt = 2; p.mode = EP_ADN;
        p.t0h = midh; p.gamh = gamh; p.beth = beth; p.stats = stats;
        p.ohh = oh;
        rung(false, false, 32, 1, NB, p);
    }

    // 8. conv3x3 chain: sc+bi1 merged, then final
    {
        GP p = {};
        p.A = wh + WO_SC; p.lda = 1152; p.sA = 0;
        p.B = oh; p.ldb = 0; p.sB = CHW;
        p.N = HW; p.sC = CHW; p.nkt = 18;
        p.mode = EP_TANH; p.dil = 1; p.bias = sc_b; p.ohh = gfh;
        p.A2 = wh + WO_BI1; p.mode2c = EP_GELU; p.dil2 = 2; p.bias2c = bi1_b; p.ohh2 = tmph;
        rung(false, true, 32, 2, NB, p);
    }
    {
        GP p = {};
        p.A = wh + WO_BI2; p.lda = 1152; p.sA = 0;
        p.B = tmph; p.ldb = 0; p.sB = CHW;
        p.N = HW; p.sC = CHW; p.nkt = 18; p.mode = EP_FINAL; p.dil = 1;
        p.bias = bi2_b; p.midh = midh; p.gfh = gfh; p.of = out;
        rung(false, true, 32, 1, NB, p);
    }
}